// round 6
// baseline (speedup 1.0000x reference)
#include <cuda_runtime.h>
#include <cuda_bf16.h>
#include <cstdint>
#include <math.h>

typedef __nv_bfloat16 bf16;

// ---- arch gate: tcgen05 only exists on arch-specific (sm_103a) targets ----
#if defined(__CUDA_ARCH__) && ( \
      defined(__CUDA_ARCH_FEAT_SM103_ALL) || \
      defined(__CUDA_ARCH_FEAT_SM100_ALL) || \
      (defined(__CUDA_ARCH_SPECIFIC__) && (__CUDA_ARCH_SPECIFIC__ == 1030 || __CUDA_ARCH_SPECIFIC__ == 1000)) )
#define HAS_TC 1
#else
#define HAS_TC 0
#endif

// ---- problem dims ----
#define M_DIM 4096
#define H_DIM 4096
#define I_DIM 11008

// ---- GEMM tile config: cg2 pair computes M=256 x N=256 ----
#define BM 128          // per CTA
#define BN 256          // across pair (each CTA stores N/2=128 B rows)
#define KC 64           // bf16 elems per K-chunk -> 128B rows (SW128 atom)
#define NTHREADS 256

// ---- smem stage layout (bytes): A hi/lo [128x64], B-half hi/lo [128x64] ----
#define OFF_AHI 0
#define OFF_ALO (16*1024)
#define OFF_BHI (32*1024)
#define OFF_BLO (48*1024)
#define STAGE_BYTES (64*1024)
#define SMEM_STAGE0 1024
#define SMEM_TOTAL (SMEM_STAGE0 + 2*STAGE_BYTES)   // 132096 B

// mbarrier offsets
#define MB_MMA0 8
#define MB_MMA1 16
#define MB_LD0  24
#define MB_LD1  32

// idesc: kind::f16, dtype=F32(1<<4), atype=BF16(1<<7), btype=BF16(1<<10),
// N=256 -> (256/8)<<17, M=256 (pair total) -> (256/16)<<24
#define MMA_IDESC ((1u<<4)|(1u<<7)|(1u<<10)|((256/8)<<17)|((256/16)<<24))

// SW128 K-major smem descriptor base (layout=2, version=1, SBO=64, LBO=1)
#define SMEM_DESC_BASE_SW128 \
    ((uint64_t(2) << 61) | (uint64_t(1) << 46) | (uint64_t(64) << 32) | (uint64_t(1) << 16))

// ---- device scratch (allocation-free rule) ----
__device__ bf16 g_x_hi [(size_t)M_DIM * H_DIM];
__device__ bf16 g_x_lo [(size_t)M_DIM * H_DIM];
__device__ bf16 g_wgu_hi[(size_t)2 * I_DIM * H_DIM];
__device__ bf16 g_wgu_lo[(size_t)2 * I_DIM * H_DIM];
__device__ bf16 g_wd_hi [(size_t)H_DIM * I_DIM];
__device__ bf16 g_wd_lo [(size_t)H_DIM * I_DIM];
__device__ bf16 g_h_hi  [(size_t)M_DIM * I_DIM];
__device__ bf16 g_h_lo  [(size_t)M_DIM * I_DIM];

// ======================= generic PTX helpers =======================

__device__ __forceinline__ uint32_t smem_u32(const void* p) {
    uint32_t a;
    asm("{ .reg .u64 t; cvta.to.shared.u64 t, %1; cvt.u32.u64 %0, t; }" : "=r"(a) : "l"(p));
    return a;
}

__device__ __forceinline__ uint32_t cluster_rank() {
    uint32_t r;
    asm("mov.u32 %0, %%cluster_ctarank;" : "=r"(r));
    return r;
}

__device__ __forceinline__ uint32_t elect_one() {
    uint32_t pred;
    asm volatile("{\n\t.reg .pred p;\n\telect.sync _|p, 0xFFFFFFFF;\n\tselp.b32 %0, 1, 0, p;\n\t}" : "=r"(pred));
    return pred;
}

__device__ __forceinline__ uint32_t swz(uint32_t off) { return off ^ ((off >> 3) & 0x70); }

__device__ __forceinline__ void cp16(uint32_t dst, const void* src) {
    asm volatile("cp.async.cg.shared.global [%0], [%1], 16;" :: "r"(dst), "l"(src) : "memory");
}

// .noinc REQUIRED (default form pre-increments pending count, self-cancelling)
__device__ __forceinline__ void cp_arrive(uint32_t mbar) {
    asm volatile("cp.async.mbarrier.arrive.noinc.shared::cta.b64 [%0];" :: "r"(mbar) : "memory");
}

__device__ __forceinline__ uint64_t make_desc(uint32_t addr) {
    return SMEM_DESC_BASE_SW128 | ((uint64_t)(addr >> 4) & 0x3FFF);
}

#define MBARRIER_INIT(mbar, count) \
    asm volatile("mbarrier.init.shared.b64 [%0], %1;" \
        :: "r"((uint32_t)(mbar)), "r"((uint32_t)(count)) : "memory")

// arrive on the same-offset barrier in cluster CTA target_rank
#define MBARRIER_ARRIVE_CLUSTER(local_mbar_addr, target_rank) \
    asm volatile( \
        "{\n\t.reg .b32 remAddr32;\n\t" \
        "mapa.shared::cluster.u32 remAddr32, %0, %1;\n\t" \
        "mbarrier.arrive.release.cluster.shared::cluster.b64 _, [remAddr32];\n\t}" \
        :: "r"((uint32_t)(local_mbar_addr)), "r"((uint32_t)(target_rank)) : "memory")

#define MBARRIER_WAIT_PARITY(mbar_addr, phase_parity) do { \
    uint32_t _mbar = (uint32_t)(mbar_addr); \
    uint32_t _parity = (uint32_t)(phase_parity); \
    uint32_t _done; \
    asm volatile( \
        "{\n\t.reg .pred p;\n\t" \
        "mbarrier.try_wait.parity.acquire.cta.shared::cta.b64 p, [%1], %2;\n\t" \
        "selp.b32 %0, 1, 0, p;\n\t}" \
        : "=r"(_done) : "r"(_mbar), "r"(_parity) : "memory"); \
    if (!_done) { \
        asm volatile( \
            "{\n\t.reg .pred P1;\n\t" \
            "WAIT_LOOP_%=:\n\t" \
            "mbarrier.try_wait.parity.acquire.cta.shared::cta.b64 P1, [%0], %1, 0x989680;\n\t" \
            "@P1 bra.uni WAIT_DONE_%=;\n\t" \
            "bra.uni WAIT_LOOP_%=;\n\t" \
            "WAIT_DONE_%=:\n\t}" \
            :: "r"(_mbar), "r"(_parity) : "memory"); \
    } \
} while (0)

#define CLUSTER_SYNC() do { \
    asm volatile("barrier.cluster.arrive.aligned;" ::: "memory"); \
    asm volatile("barrier.cluster.wait.aligned;" ::: "memory"); \
} while (0)

// ======================= tcgen05 cg2 helpers =======================

__device__ __forceinline__ void mma_ss_cg2(uint32_t d, uint64_t ad, uint64_t bd,
                                           uint32_t idesc, uint32_t en) {
    asm volatile(
        "{\n\t"
        ".reg .pred p;\n\t"
        "setp.ne.u32 p, %4, 0;\n\t"
        "tcgen05.mma.cta_group::2.kind::f16 [%0], %1, %2, %3, {%5, %5, %5, %5, %5, %5, %5, %5}, p;\n\t"
        "}"
        :: "r"(d), "l"(ad), "l"(bd), "r"(idesc), "r"(en), "r"(0u)
        : "memory");
}

__device__ __forceinline__ void tc_alloc_cg2(uint32_t smem_result_addr, uint32_t nCols) {
    asm volatile("tcgen05.alloc.cta_group::2.sync.aligned.shared::cta.b32 [%0], %1;"
        :: "r"(smem_result_addr), "r"(nCols) : "memory");
}
__device__ __forceinline__ void tc_dealloc_cg2(uint32_t tmem_addr, uint32_t nCols) {
    asm volatile("tcgen05.dealloc.cta_group::2.sync.aligned.b32 %0, %1;"
        :: "r"(tmem_addr), "r"(nCols));
}
__device__ __forceinline__ void tc_relinquish_cg2() {
    asm volatile("tcgen05.relinquish_alloc_permit.cta_group::2.sync.aligned;");
}
__device__ __forceinline__ void tc_commit_mc_cg2(uint32_t mbar, uint16_t mask) {
    asm volatile("tcgen05.commit.cta_group::2.mbarrier::arrive::one.shared::cluster.multicast::cluster.b64 [%0], %1;"
        :: "r"(mbar), "h"(mask) : "memory");
}
__device__ __forceinline__ void tc_fence_after() {
    asm volatile("tcgen05.fence::after_thread_sync;" ::: "memory");
}
__device__ __forceinline__ void tc_wait_ld() {
    asm volatile("tcgen05.wait::ld.sync.aligned;" ::: "memory");
}
__device__ __forceinline__ void tc_ld32(uint32_t* r, uint32_t tmem_addr) {
    asm volatile(
        "tcgen05.ld.sync.aligned.32x32b.x32.b32 "
        "{%0, %1, %2, %3, %4, %5, %6, %7, "
        " %8, %9, %10, %11, %12, %13, %14, %15, "
        " %16, %17, %18, %19, %20, %21, %22, %23, "
        " %24, %25, %26, %27, %28, %29, %30, %31}, [%32];"
        : "=r"(r[0]),  "=r"(r[1]),  "=r"(r[2]),  "=r"(r[3]),
          "=r"(r[4]),  "=r"(r[5]),  "=r"(r[6]),  "=r"(r[7]),
          "=r"(r[8]),  "=r"(r[9]),  "=r"(r[10]), "=r"(r[11]),
          "=r"(r[12]), "=r"(r[13]), "=r"(r[14]), "=r"(r[15]),
          "=r"(r[16]), "=r"(r[17]), "=r"(r[18]), "=r"(r[19]),
          "=r"(r[20]), "=r"(r[21]), "=r"(r[22]), "=r"(r[23]),
          "=r"(r[24]), "=r"(r[25]), "=r"(r[26]), "=r"(r[27]),
          "=r"(r[28]), "=r"(r[29]), "=r"(r[30]), "=r"(r[31])
        : "r"(tmem_addr));
}

// ======================= tile loader (128 loader threads) =======================
// Per CTA per chunk: A hi/lo [128x64 bf16] + B-half hi/lo [128x64 bf16]
// = 4096 x 16B units / 128 threads = 32 cp16 each (8 per tensor).
__device__ __forceinline__ void load_chunk128(
    uint32_t sbase, int t, int k0, int K,
    const bf16* a_hi, const bf16* a_lo,
    const bf16* bh_hi, const bf16* bh_lo)
{
#pragma unroll
    for (int j = 0; j < 8; ++j) {
        int cc = t + j * 128, row = cc >> 3, col = cc & 7;
        cp16(sbase + OFF_AHI + swz((uint32_t)row * 128 + col * 16),
             a_hi + (size_t)row * K + k0 + col * 8);
    }
#pragma unroll
    for (int j = 0; j < 8; ++j) {
        int cc = t + j * 128, row = cc >> 3, col = cc & 7;
        cp16(sbase + OFF_ALO + swz((uint32_t)row * 128 + col * 16),
             a_lo + (size_t)row * K + k0 + col * 8);
    }
#pragma unroll
    for (int j = 0; j < 8; ++j) {
        int cc = t + j * 128, row = cc >> 3, col = cc & 7;
        cp16(sbase + OFF_BHI + swz((uint32_t)row * 128 + col * 16),
             bh_hi + (size_t)row * K + k0 + col * 8);
    }
#pragma unroll
    for (int j = 0; j < 8; ++j) {
        int cc = t + j * 128, row = cc >> 3, col = cc & 7;
        cp16(sbase + OFF_BLO + swz((uint32_t)row * 128 + col * 16),
             bh_lo + (size_t)row * K + k0 + col * 8);
    }
}

// ======================= fused GEMM (cg2 pair) =======================
// Pair = 2 CTAs along blockIdx.x (cluster (2,1,1)); rank r owns M rows mbx*128.
// MODE 1: gu slice; B rank0 = gate rows, rank1 = up rows (N=256 = [gate|up]);
//         epilogue SwiGLU -> h hi/lo.  grid (M/128, I/128).
// MODE 0: out = h @ Wd^T; rank r holds B rows nb*256 + r*128.  grid (M/128, H/256).
template<int MODE>
__global__ void __launch_bounds__(NTHREADS, 1) __cluster_dims__(2, 1, 1)
mlp_gemm(const bf16* __restrict__ A_hi, const bf16* __restrict__ A_lo,
         const bf16* __restrict__ B_hi, const bf16* __restrict__ B_lo,
         const bf16* __restrict__ B1_hi, const bf16* __restrict__ B1_lo,
         int K, int ldout,
         float* __restrict__ Cout,
         bf16* __restrict__ Hhi, bf16* __restrict__ Hlo)
{
    extern __shared__ __align__(1024) char smem[];
    const int tid = threadIdx.x;
    const int mbx = blockIdx.x, nb = blockIdx.y;

    const bf16* a_hi = A_hi + (size_t)mbx * BM * K;
    const bf16* a_lo = A_lo + (size_t)mbx * BM * K;

#if HAS_TC
    // ---------------- cg2 tcgen05 warp-specialized path ----------------
    const uint32_t sb = smem_u32(smem);
    const int wid = tid >> 5;
    const uint32_t rank = cluster_rank();

    // B half for this rank (128 rows)
    const bf16 *bh_hi, *bh_lo;
    if (MODE == 1) {
        size_t o = (size_t)nb * 128 * K;
        bh_hi = (rank ? B1_hi : B_hi) + o;
        bh_lo = (rank ? B1_lo : B_lo) + o;
    } else {
        size_t o = ((size_t)nb * 256 + rank * 128) * K;
        bh_hi = B_hi + o;
        bh_lo = B_lo + o;
    }

    if (wid == 0) tc_alloc_cg2(sb + 0, 256);
    if (tid == 0) {
        MBARRIER_INIT(sb + MB_MMA0, 1);
        MBARRIER_INIT(sb + MB_MMA1, 1);
        const uint32_t ldc = (rank == 0) ? 129u : 128u;   // +1 remote relay on leader
        MBARRIER_INIT(sb + MB_LD0, ldc);
        MBARRIER_INIT(sb + MB_LD1, ldc);
    }
    __syncthreads();
    uint32_t tmem;
    asm volatile("ld.shared.b32 %0, [%1];" : "=r"(tmem) : "r"(sb));

    // all mbarriers initialized in both CTAs before any cross-CTA traffic
    CLUSTER_SYNC();

    const int nch = K / KC;          // 64 (GEMM1) / 172 (GEMM2), both even

    if (wid >= 4) {
        // ---- loader warps: 128 threads, local A + local B-half ----
        const int t = tid - 128;
        load_chunk128(sb + SMEM_STAGE0,               t, 0,  K, a_hi, a_lo, bh_hi, bh_lo);
        cp_arrive(sb + MB_LD0);
        load_chunk128(sb + SMEM_STAGE0 + STAGE_BYTES, t, KC, K, a_hi, a_lo, bh_hi, bh_lo);
        cp_arrive(sb + MB_LD1);

        int phm0 = 0, phm1 = 0;
        for (int i = 2; i < nch; ++i) {
            const int p = i & 1;
            if (p == 0) { MBARRIER_WAIT_PARITY(sb + MB_MMA0, phm0); phm0 ^= 1; }
            else        { MBARRIER_WAIT_PARITY(sb + MB_MMA1, phm1); phm1 ^= 1; }
            load_chunk128(sb + SMEM_STAGE0 + (uint32_t)p * STAGE_BYTES, t, i * KC, K,
                          a_hi, a_lo, bh_hi, bh_lo);
            cp_arrive(sb + MB_LD0 + p * 8);
        }
    } else if (wid == 0) {
        if (rank == 0) {
            // ---- leader: issue cg2 MMAs; never waits for MMA completion ----
            int phl0 = 0, phl1 = 0;
            for (int i = 0; i < nch; ++i) {
                const int p = i & 1;
                if (p == 0) { MBARRIER_WAIT_PARITY(sb + MB_LD0, phl0); phl0 ^= 1; }
                else        { MBARRIER_WAIT_PARITY(sb + MB_LD1, phl1); phl1 ^= 1; }
                if (elect_one()) {
                    asm volatile("fence.proxy.async;" ::: "memory");
                    const uint32_t stage = sb + SMEM_STAGE0 + (uint32_t)p * STAGE_BYTES;
                    const uint64_t adh = make_desc(stage + OFF_AHI);
                    const uint64_t adl = make_desc(stage + OFF_ALO);
                    const uint64_t bdh = make_desc(stage + OFF_BHI);
                    const uint64_t bdl = make_desc(stage + OFF_BLO);
                    uint32_t en = (i != 0) ? 1u : 0u;
#pragma unroll
                    for (int kk = 0; kk < 4; ++kk) { mma_ss_cg2(tmem, adh + kk*2, bdh + kk*2, MMA_IDESC, en); en = 1; }
#pragma unroll
                    for (int kk = 0; kk < 4; ++kk) mma_ss_cg2(tmem, adh + kk*2, bdl + kk*2, MMA_IDESC, 1);
#pragma unroll
                    for (int kk = 0; kk < 4; ++kk) mma_ss_cg2(tmem, adl + kk*2, bdh + kk*2, MMA_IDESC, 1);
                    tc_commit_mc_cg2(sb + MB_MMA0 + p * 8, 0x3);   // arrive both CTAs
                }
            }
        } else {
            // ---- follower relay: local load-done -> leader's LD barrier ----
            int phl0 = 0, phl1 = 0;
            for (int i = 0; i < nch; ++i) {
                const int p = i & 1;
                if (p == 0) { MBARRIER_WAIT_PARITY(sb + MB_LD0, phl0); phl0 ^= 1; }
                else        { MBARRIER_WAIT_PARITY(sb + MB_LD1, phl1); phl1 ^= 1; }
                if (elect_one()) {
                    asm volatile("fence.proxy.async;" ::: "memory");
                    MBARRIER_ARRIVE_CLUSTER(sb + MB_LD0 + p * 8, 0);
                }
            }
        }
        // both ranks: wait final MMA commits (each buffer committed nch/2
        // times; loaders consumed parities up to nch/2-2 -> final = (nch/2-1)&1)
        const int fpar = ((nch / 2) - 1) & 1;
        MBARRIER_WAIT_PARITY(sb + MB_MMA0, fpar);
        MBARRIER_WAIT_PARITY(sb + MB_MMA1, fpar);
    }
    __syncthreads();
    tc_fence_after();

    // ---- epilogue: each CTA reads its own 128 rows x 256 cols of D ----
    if (MODE == 1) {
        bf16* sH = reinterpret_cast<bf16*>(smem);                 // [128][130]
        bf16* sL = sH + 128 * 130;
        if (tid < 128) {
#pragma unroll
            for (int c0 = 0; c0 < 128; c0 += 32) {
                uint32_t gr[32], ur[32];
                tc_ld32(gr, tmem + c0);
                tc_ld32(ur, tmem + 128 + c0);
                tc_wait_ld();
#pragma unroll
                for (int j = 0; j < 32; ++j) {
                    float g = __uint_as_float(gr[j]);
                    float u = __uint_as_float(ur[j]);
                    float h = g * u / (1.0f + __expf(-g));
                    bf16 hv = __float2bfloat16(h);
                    sH[tid * 130 + c0 + j] = hv;
                    sL[tid * 130 + c0 + j] = __float2bfloat16(h - __bfloat162float(hv));
                }
            }
        }
        __syncthreads();
        const size_t obase = (size_t)(mbx * BM) * ldout + (size_t)nb * 128;
#pragma unroll 4
        for (int u = tid; u < 128 * 64; u += NTHREADS) {
            int r = u >> 6, cu = u & 63;
            __nv_bfloat162 vh = *reinterpret_cast<__nv_bfloat162*>(&sH[r * 130 + cu * 2]);
            __nv_bfloat162 vl = *reinterpret_cast<__nv_bfloat162*>(&sL[r * 130 + cu * 2]);
            *reinterpret_cast<__nv_bfloat162*>(Hhi + obase + (size_t)r * ldout + cu * 2) = vh;
            *reinterpret_cast<__nv_bfloat162*>(Hlo + obase + (size_t)r * ldout + cu * 2) = vl;
        }
    } else {
        float* sC = reinterpret_cast<float*>(smem);               // [128][257]
        if (tid < 128) {
#pragma unroll
            for (int c0 = 0; c0 < 256; c0 += 32) {
                uint32_t dr[32];
                tc_ld32(dr, tmem + c0);
                tc_wait_ld();
#pragma unroll
                for (int j = 0; j < 32; ++j)
                    sC[tid * 257 + c0 + j] = __uint_as_float(dr[j]);
            }
        }
        __syncthreads();
        const size_t obase = (size_t)(mbx * BM) * ldout + (size_t)nb * 256;
#pragma unroll 4
        for (int u = tid; u < 128 * 256; u += NTHREADS) {
            int r = u >> 8, col = u & 255;
            Cout[obase + (size_t)r * ldout + col] = sC[r * 257 + col];
        }
    }
    __syncthreads();
    CLUSTER_SYNC();                       // peer MMAs fully drained on both sides
    if (wid == 0) {
        tc_relinquish_cg2();
        tc_dealloc_cg2(tmem, 256);
    }
    CLUSTER_SYNC();

#else
    // ---------------- SIMT fallback (plain sm_103 target) ----------------
    const size_t boff = (MODE == 1) ? (size_t)nb * 128 * K : (size_t)nb * 256 * K;
    const bf16* b0_hi = B_hi + boff;
    const bf16* b0_lo = B_lo + boff;
    const bf16* b1_hi = (MODE == 1) ? (B1_hi + boff) : (B_hi + boff + (size_t)128 * K);
    const bf16* b1_lo = (MODE == 1) ? (B1_lo + boff) : (B_lo + boff + (size_t)128 * K);

    float* fA  = reinterpret_cast<float*>(smem);          // [8][128]
    float* fB0 = fA  + 8 * 128;
    float* fB1 = fB0 + 8 * 128;

    const int tx = tid & 15;
    const int ty = tid >> 4;
    const int lr = tid >> 1;
    const int lc = (tid & 1) << 2;

    float acc0[8][8], acc1[8][8];
#pragma unroll
    for (int i = 0; i < 8; i++)
#pragma unroll
        for (int j = 0; j < 8; j++) { acc0[i][j] = 0.0f; acc1[i][j] = 0.0f; }

    for (int k0 = 0; k0 < K; k0 += 8) {
        __syncthreads();
#pragma unroll
        for (int c = 0; c < 4; ++c) {
            int k = k0 + lc + c;
            size_t off = (size_t)lr * K + k;
            fA [(lc + c) * 128 + lr] = __bfloat162float(a_hi[off]) + __bfloat162float(a_lo[off]);
            fB0[(lc + c) * 128 + lr] = __bfloat162float(b0_hi[off]) + __bfloat162float(b0_lo[off]);
            fB1[(lc + c) * 128 + lr] = __bfloat162float(b1_hi[off]) + __bfloat162float(b1_lo[off]);
        }
        __syncthreads();
#pragma unroll
        for (int k = 0; k < 8; k++) {
            float ra[8], rb0[8], rb1[8];
#pragma unroll
            for (int i = 0; i < 8; i++) ra[i]  = fA [k * 128 + ty * 8 + i];
#pragma unroll
            for (int j = 0; j < 8; j++) { rb0[j] = fB0[k * 128 + tx * 8 + j]; rb1[j] = fB1[k * 128 + tx * 8 + j]; }
#pragma unroll
            for (int i = 0; i < 8; i++)
#pragma unroll
                for (int j = 0; j < 8; j++) {
                    acc0[i][j] = fmaf(ra[i], rb0[j], acc0[i][j]);
                    acc1[i][j] = fmaf(ra[i], rb1[j], acc1[i][j]);
                }
        }
    }

    if (MODE == 1) {
#pragma unroll
        for (int i = 0; i < 8; i++) {
            int m = mbx * BM + ty * 8 + i;
            bf16* hh = Hhi + (size_t)m * ldout + (size_t)nb * 128 + tx * 8;
            bf16* hl = Hlo + (size_t)m * ldout + (size_t)nb * 128 + tx * 8;
#pragma unroll
            for (int j = 0; j < 8; j++) {
                float g = acc0[i][j], u = acc1[i][j];
                float h = g * u / (1.0f + __expf(-g));
                bf16 hv = __float2bfloat16(h);
                hh[j] = hv;
                hl[j] = __float2bfloat16(h - __bfloat162float(hv));
            }
        }
    } else {
#pragma unroll
        for (int i = 0; i < 8; i++) {
            int m = mbx * BM + ty * 8 + i;
            float* co = Cout + (size_t)m * ldout + (size_t)nb * 256 + tx * 8;
#pragma unroll
            for (int j = 0; j < 8; j++) { co[j] = acc0[i][j]; co[128 + j] = acc1[i][j]; }
        }
    }
#endif
}

// ======================= fp32 -> bf16 hi/lo split =======================
__global__ void split_kernel(const float4* __restrict__ src,
                             __nv_bfloat162* __restrict__ hi,
                             __nv_bfloat162* __restrict__ lo, long n4)
{
    long i = (long)blockIdx.x * blockDim.x + threadIdx.x;
    if (i >= n4) return;
    float4 v = src[i];
    bf16 h0 = __float2bfloat16(v.x);
    bf16 h1 = __float2bfloat16(v.y);
    bf16 h2 = __float2bfloat16(v.z);
    bf16 h3 = __float2bfloat16(v.w);
    bf16 l0 = __float2bfloat16(v.x - __bfloat162float(h0));
    bf16 l1 = __float2bfloat16(v.y - __bfloat162float(h1));
    bf16 l2 = __float2bfloat16(v.z - __bfloat162float(h2));
    bf16 l3 = __float2bfloat16(v.w - __bfloat162float(h3));
    hi[2*i]   = __halves2bfloat162(h0, h1);
    hi[2*i+1] = __halves2bfloat162(h2, h3);
    lo[2*i]   = __halves2bfloat162(l0, l1);
    lo[2*i+1] = __halves2bfloat162(l2, l3);
}

// ======================= launch =======================
extern "C" void kernel_launch(void* const* d_in, const int* in_sizes, int n_in,
                              void* d_out, int out_size)
{
    const float* x   = (const float*)d_in[0];
    const float* wgu = (const float*)d_in[1];
    const float* wd  = (const float*)d_in[2];
    float* out       = (float*)d_out;

    bf16 *x_hi, *x_lo, *wgu_hi, *wgu_lo, *wd_hi, *wd_lo, *h_hi, *h_lo;
    cudaGetSymbolAddress((void**)&x_hi,  g_x_hi);
    cudaGetSymbolAddress((void**)&x_lo,  g_x_lo);
    cudaGetSymbolAddress((void**)&wgu_hi, g_wgu_hi);
    cudaGetSymbolAddress((void**)&wgu_lo, g_wgu_lo);
    cudaGetSymbolAddress((void**)&wd_hi, g_wd_hi);
    cudaGetSymbolAddress((void**)&wd_lo, g_wd_lo);
    cudaGetSymbolAddress((void**)&h_hi,  g_h_hi);
    cudaGetSymbolAddress((void**)&h_lo,  g_h_lo);

    cudaFuncSetAttribute(mlp_gemm<0>, cudaFuncAttributeMaxDynamicSharedMemorySize, SMEM_TOTAL);
    cudaFuncSetAttribute(mlp_gemm<1>, cudaFuncAttributeMaxDynamicSharedMemorySize, SMEM_TOTAL);

    // split inputs into bf16 hi/lo
    {
        long n4 = (long)M_DIM * H_DIM / 4;
        split_kernel<<<(unsigned)((n4 + 255) / 256), 256>>>(
            (const float4*)x, (__nv_bfloat162*)x_hi, (__nv_bfloat162*)x_lo, n4);
    }
    {
        long n4 = (long)2 * I_DIM * H_DIM / 4;
        split_kernel<<<(unsigned)((n4 + 255) / 256), 256>>>(
            (const float4*)wgu, (__nv_bfloat162*)wgu_hi, (__nv_bfloat162*)wgu_lo, n4);
    }
    {
        long n4 = (long)H_DIM * I_DIM / 4;
        split_kernel<<<(unsigned)((n4 + 255) / 256), 256>>>(
            (const float4*)wd, (__nv_bfloat162*)wd_hi, (__nv_bfloat162*)wd_lo, n4);
    }

    // GEMM1 (fused SwiGLU + h split): grid (M/128, I/128), clusters of 2 along x
    mlp_gemm<1><<<dim3(M_DIM / BM, I_DIM / 128), NTHREADS, SMEM_TOTAL>>>(
        x_hi, x_lo,
        wgu_hi, wgu_lo,
        wgu_hi + (size_t)I_DIM * H_DIM, wgu_lo + (size_t)I_DIM * H_DIM,
        H_DIM, I_DIM,
        nullptr, h_hi, h_lo);

    // GEMM2: out = h @ Wd^T: grid (M/128, H/256), clusters of 2 along x
    mlp_gemm<0><<<dim3(M_DIM / BM, H_DIM / 256), NTHREADS, SMEM_TOTAL>>>(
        h_hi, h_lo,
        wd_hi, wd_lo,
        nullptr, nullptr,
        I_DIM, H_DIM,
        out, nullptr, nullptr);
}

// round 7
// speedup vs baseline: 1.1374x; 1.1374x over previous
#include <cuda_runtime.h>
#include <cuda_bf16.h>
#include <cstdint>
#include <math.h>

typedef __nv_bfloat16 bf16;

// ---- arch gate: tcgen05 only exists on arch-specific (sm_103a) targets ----
#if defined(__CUDA_ARCH__) && ( \
      defined(__CUDA_ARCH_FEAT_SM103_ALL) || \
      defined(__CUDA_ARCH_FEAT_SM100_ALL) || \
      (defined(__CUDA_ARCH_SPECIFIC__) && (__CUDA_ARCH_SPECIFIC__ == 1030 || __CUDA_ARCH_SPECIFIC__ == 1000)) )
#define HAS_TC 1
#else
#define HAS_TC 0
#endif

// ---- problem dims ----
#define M_DIM 4096
#define H_DIM 4096
#define I_DIM 11008

// ---- GEMM tile config: cg2 pair computes M=256 x N=256 ----
#define BM 128          // per CTA
#define KC 64           // bf16 elems per K-chunk -> 128B rows (SW128 atom)
#define NTHREADS 256
#define NSTAGE 3

// ---- smem stage layout (bytes): A hi/lo [128x64], B-half hi/lo [128x64] ----
#define OFF_AHI 0
#define OFF_ALO (16*1024)
#define OFF_BHI (32*1024)
#define OFF_BLO (48*1024)
#define STAGE_BYTES (64*1024)
#define SMEM_STAGE0 1024
#define SMEM_TOTAL (SMEM_STAGE0 + NSTAGE*STAGE_BYTES)   // 197632 B

// mbarrier offsets: MMA[s] at 8+8s, LD[s] at 40+8s
#define MB_MMA(s) (8  + (s)*8)
#define MB_LD(s)  (40 + (s)*8)

// idesc: kind::f16, dtype=F32(1<<4), atype=BF16(1<<7), btype=BF16(1<<10),
// N=256 -> (256/8)<<17, M=256 (pair total) -> (256/16)<<24
#define MMA_IDESC ((1u<<4)|(1u<<7)|(1u<<10)|((256/8)<<17)|((256/16)<<24))

// SW128 K-major smem descriptor base (layout=2, version=1, SBO=64, LBO=1)
#define SMEM_DESC_BASE_SW128 \
    ((uint64_t(2) << 61) | (uint64_t(1) << 46) | (uint64_t(64) << 32) | (uint64_t(1) << 16))

// ---- device scratch (allocation-free rule) ----
__device__ bf16 g_x_hi [(size_t)M_DIM * H_DIM];
__device__ bf16 g_x_lo [(size_t)M_DIM * H_DIM];
__device__ bf16 g_wgu_hi[(size_t)2 * I_DIM * H_DIM];
__device__ bf16 g_wgu_lo[(size_t)2 * I_DIM * H_DIM];
__device__ bf16 g_wd_hi [(size_t)H_DIM * I_DIM];
__device__ bf16 g_wd_lo [(size_t)H_DIM * I_DIM];
__device__ bf16 g_h_hi  [(size_t)M_DIM * I_DIM];
__device__ bf16 g_h_lo  [(size_t)M_DIM * I_DIM];

// ======================= generic PTX helpers =======================

__device__ __forceinline__ uint32_t smem_u32(const void* p) {
    uint32_t a;
    asm("{ .reg .u64 t; cvta.to.shared.u64 t, %1; cvt.u32.u64 %0, t; }" : "=r"(a) : "l"(p));
    return a;
}

__device__ __forceinline__ uint32_t cluster_rank() {
    uint32_t r;
    asm("mov.u32 %0, %%cluster_ctarank;" : "=r"(r));
    return r;
}

__device__ __forceinline__ uint32_t elect_one() {
    uint32_t pred;
    asm volatile("{\n\t.reg .pred p;\n\telect.sync _|p, 0xFFFFFFFF;\n\tselp.b32 %0, 1, 0, p;\n\t}" : "=r"(pred));
    return pred;
}

__device__ __forceinline__ uint32_t swz(uint32_t off) { return off ^ ((off >> 3) & 0x70); }

__device__ __forceinline__ void cp16(uint32_t dst, const void* src) {
    asm volatile("cp.async.cg.shared.global [%0], [%1], 16;" :: "r"(dst), "l"(src) : "memory");
}

// .noinc REQUIRED (default form pre-increments pending count, self-cancelling)
__device__ __forceinline__ void cp_arrive(uint32_t mbar) {
    asm volatile("cp.async.mbarrier.arrive.noinc.shared::cta.b64 [%0];" :: "r"(mbar) : "memory");
}

__device__ __forceinline__ uint64_t make_desc(uint32_t addr) {
    return SMEM_DESC_BASE_SW128 | ((uint64_t)(addr >> 4) & 0x3FFF);
}

#define MBARRIER_INIT(mbar, count) \
    asm volatile("mbarrier.init.shared.b64 [%0], %1;" \
        :: "r"((uint32_t)(mbar)), "r"((uint32_t)(count)) : "memory")

// arrive on the same-offset barrier in cluster CTA target_rank
#define MBARRIER_ARRIVE_CLUSTER(local_mbar_addr, target_rank) \
    asm volatile( \
        "{\n\t.reg .b32 remAddr32;\n\t" \
        "mapa.shared::cluster.u32 remAddr32, %0, %1;\n\t" \
        "mbarrier.arrive.release.cluster.shared::cluster.b64 _, [remAddr32];\n\t}" \
        :: "r"((uint32_t)(local_mbar_addr)), "r"((uint32_t)(target_rank)) : "memory")

#define MBARRIER_WAIT_PARITY(mbar_addr, phase_parity) do { \
    uint32_t _mbar = (uint32_t)(mbar_addr); \
    uint32_t _parity = (uint32_t)(phase_parity); \
    uint32_t _done; \
    asm volatile( \
        "{\n\t.reg .pred p;\n\t" \
        "mbarrier.try_wait.parity.acquire.cta.shared::cta.b64 p, [%1], %2;\n\t" \
        "selp.b32 %0, 1, 0, p;\n\t}" \
        : "=r"(_done) : "r"(_mbar), "r"(_parity) : "memory"); \
    if (!_done) { \
        asm volatile( \
            "{\n\t.reg .pred P1;\n\t" \
            "WAIT_LOOP_%=:\n\t" \
            "mbarrier.try_wait.parity.acquire.cta.shared::cta.b64 P1, [%0], %1, 0x989680;\n\t" \
            "@P1 bra.uni WAIT_DONE_%=;\n\t" \
            "bra.uni WAIT_LOOP_%=;\n\t" \
            "WAIT_DONE_%=:\n\t}" \
            :: "r"(_mbar), "r"(_parity) : "memory"); \
    } \
} while (0)

#define CLUSTER_SYNC() do { \
    asm volatile("barrier.cluster.arrive.aligned;" ::: "memory"); \
    asm volatile("barrier.cluster.wait.aligned;" ::: "memory"); \
} while (0)

// ======================= tcgen05 cg2 helpers =======================

__device__ __forceinline__ void mma_ss_cg2(uint32_t d, uint64_t ad, uint64_t bd,
                                           uint32_t idesc, uint32_t en) {
    asm volatile(
        "{\n\t"
        ".reg .pred p;\n\t"
        "setp.ne.u32 p, %4, 0;\n\t"
        "tcgen05.mma.cta_group::2.kind::f16 [%0], %1, %2, %3, {%5, %5, %5, %5, %5, %5, %5, %5}, p;\n\t"
        "}"
        :: "r"(d), "l"(ad), "l"(bd), "r"(idesc), "r"(en), "r"(0u)
        : "memory");
}

__device__ __forceinline__ void tc_alloc_cg2(uint32_t smem_result_addr, uint32_t nCols) {
    asm volatile("tcgen05.alloc.cta_group::2.sync.aligned.shared::cta.b32 [%0], %1;"
        :: "r"(smem_result_addr), "r"(nCols) : "memory");
}
__device__ __forceinline__ void tc_dealloc_cg2(uint32_t tmem_addr, uint32_t nCols) {
    asm volatile("tcgen05.dealloc.cta_group::2.sync.aligned.b32 %0, %1;"
        :: "r"(tmem_addr), "r"(nCols));
}
__device__ __forceinline__ void tc_relinquish_cg2() {
    asm volatile("tcgen05.relinquish_alloc_permit.cta_group::2.sync.aligned;");
}
__device__ __forceinline__ void tc_commit_mc_cg2(uint32_t mbar, uint16_t mask) {
    asm volatile("tcgen05.commit.cta_group::2.mbarrier::arrive::one.shared::cluster.multicast::cluster.b64 [%0], %1;"
        :: "r"(mbar), "h"(mask) : "memory");
}
__device__ __forceinline__ void tc_fence_after() {
    asm volatile("tcgen05.fence::after_thread_sync;" ::: "memory");
}
__device__ __forceinline__ void tc_wait_ld() {
    asm volatile("tcgen05.wait::ld.sync.aligned;" ::: "memory");
}
__device__ __forceinline__ void tc_ld32(uint32_t* r, uint32_t tmem_addr) {
    asm volatile(
        "tcgen05.ld.sync.aligned.32x32b.x32.b32 "
        "{%0, %1, %2, %3, %4, %5, %6, %7, "
        " %8, %9, %10, %11, %12, %13, %14, %15, "
        " %16, %17, %18, %19, %20, %21, %22, %23, "
        " %24, %25, %26, %27, %28, %29, %30, %31}, [%32];"
        : "=r"(r[0]),  "=r"(r[1]),  "=r"(r[2]),  "=r"(r[3]),
          "=r"(r[4]),  "=r"(r[5]),  "=r"(r[6]),  "=r"(r[7]),
          "=r"(r[8]),  "=r"(r[9]),  "=r"(r[10]), "=r"(r[11]),
          "=r"(r[12]), "=r"(r[13]), "=r"(r[14]), "=r"(r[15]),
          "=r"(r[16]), "=r"(r[17]), "=r"(r[18]), "=r"(r[19]),
          "=r"(r[20]), "=r"(r[21]), "=r"(r[22]), "=r"(r[23]),
          "=r"(r[24]), "=r"(r[25]), "=r"(r[26]), "=r"(r[27]),
          "=r"(r[28]), "=r"(r[29]), "=r"(r[30]), "=r"(r[31])
        : "r"(tmem_addr));
}

// ======================= tile loader (128 loader threads) =======================
// Per CTA per chunk: A hi/lo [128x64 bf16] + B-half hi/lo [128x64 bf16]
// = 4096 x 16B units / 128 threads = 32 cp16 each (8 per tensor).
__device__ __forceinline__ void load_chunk128(
    uint32_t sbase, int t, int k0, int K,
    const bf16* a_hi, const bf16* a_lo,
    const bf16* bh_hi, const bf16* bh_lo)
{
#pragma unroll
    for (int j = 0; j < 8; ++j) {
        int cc = t + j * 128, row = cc >> 3, col = cc & 7;
        cp16(sbase + OFF_AHI + swz((uint32_t)row * 128 + col * 16),
             a_hi + (size_t)row * K + k0 + col * 8);
    }
#pragma unroll
    for (int j = 0; j < 8; ++j) {
        int cc = t + j * 128, row = cc >> 3, col = cc & 7;
        cp16(sbase + OFF_ALO + swz((uint32_t)row * 128 + col * 16),
             a_lo + (size_t)row * K + k0 + col * 8);
    }
#pragma unroll
    for (int j = 0; j < 8; ++j) {
        int cc = t + j * 128, row = cc >> 3, col = cc & 7;
        cp16(sbase + OFF_BHI + swz((uint32_t)row * 128 + col * 16),
             bh_hi + (size_t)row * K + k0 + col * 8);
    }
#pragma unroll
    for (int j = 0; j < 8; ++j) {
        int cc = t + j * 128, row = cc >> 3, col = cc & 7;
        cp16(sbase + OFF_BLO + swz((uint32_t)row * 128 + col * 16),
             bh_lo + (size_t)row * K + k0 + col * 8);
    }
}

// ======================= fused GEMM (cg2 pair, 3-stage ring) =======================
// Pair = 2 CTAs along blockIdx.x (cluster (2,1,1)); rank r owns M rows mbx*128.
// MODE 1: gu slice; B rank0 = gate rows, rank1 = up rows (N=256 = [gate|up]);
//         epilogue SwiGLU -> h hi/lo.  grid (M/128, I/128).
// MODE 0: out = h @ Wd^T; rank r holds B rows nb*256 + r*128.  grid (M/128, H/256).
template<int MODE>
__global__ void __launch_bounds__(NTHREADS, 1) __cluster_dims__(2, 1, 1)
mlp_gemm(const bf16* __restrict__ A_hi, const bf16* __restrict__ A_lo,
         const bf16* __restrict__ B_hi, const bf16* __restrict__ B_lo,
         const bf16* __restrict__ B1_hi, const bf16* __restrict__ B1_lo,
         int K, int ldout,
         float* __restrict__ Cout,
         bf16* __restrict__ Hhi, bf16* __restrict__ Hlo)
{
    extern __shared__ __align__(1024) char smem[];
    const int tid = threadIdx.x;
    const int mbx = blockIdx.x, nb = blockIdx.y;

    const bf16* a_hi = A_hi + (size_t)mbx * BM * K;
    const bf16* a_lo = A_lo + (size_t)mbx * BM * K;

#if HAS_TC
    // ---------------- cg2 tcgen05 warp-specialized path ----------------
    const uint32_t sb = smem_u32(smem);
    const int wid = tid >> 5;
    const uint32_t rank = cluster_rank();

    // B half for this rank (128 rows)
    const bf16 *bh_hi, *bh_lo;
    if (MODE == 1) {
        size_t o = (size_t)nb * 128 * K;
        bh_hi = (rank ? B1_hi : B_hi) + o;
        bh_lo = (rank ? B1_lo : B_lo) + o;
    } else {
        size_t o = ((size_t)nb * 256 + rank * 128) * K;
        bh_hi = B_hi + o;
        bh_lo = B_lo + o;
    }

    if (wid == 0) tc_alloc_cg2(sb + 0, 256);
    if (tid == 0) {
        const uint32_t ldc = (rank == 0) ? 129u : 128u;   // +1 remote relay on leader
#pragma unroll
        for (int s = 0; s < NSTAGE; ++s) {
            MBARRIER_INIT(sb + MB_MMA(s), 1);
            MBARRIER_INIT(sb + MB_LD(s), ldc);
        }
    }
    __syncthreads();
    uint32_t tmem;
    asm volatile("ld.shared.b32 %0, [%1];" : "=r"(tmem) : "r"(sb));

    // all mbarriers initialized in both CTAs before any cross-CTA traffic
    CLUSTER_SYNC();

    const int nch = K / KC;          // 64 (GEMM1) / 172 (GEMM2)

    if (wid >= 4) {
        // ---- loader warps: 128 threads, local A + local B-half ----
        const int t = tid - 128;
        for (int i = 0; i < nch; ++i) {
            const int s = i % NSTAGE;
            if (i >= NSTAGE) {
                // buffer s last used by chunk i-3 (use index i/3 - 1)
                MBARRIER_WAIT_PARITY(sb + MB_MMA(s), ((i / NSTAGE) - 1) & 1);
            }
            load_chunk128(sb + SMEM_STAGE0 + (uint32_t)s * STAGE_BYTES, t, i * KC, K,
                          a_hi, a_lo, bh_hi, bh_lo);
            cp_arrive(sb + MB_LD(s));
        }
    } else if (wid == 0) {
        if (rank == 0) {
            // ---- leader: issue cg2 MMAs; never waits for MMA completion ----
            for (int i = 0; i < nch; ++i) {
                const int s = i % NSTAGE;
                MBARRIER_WAIT_PARITY(sb + MB_LD(s), (i / NSTAGE) & 1);
                if (elect_one()) {
                    asm volatile("fence.proxy.async;" ::: "memory");
                    const uint32_t stage = sb + SMEM_STAGE0 + (uint32_t)s * STAGE_BYTES;
                    const uint64_t adh = make_desc(stage + OFF_AHI);
                    const uint64_t adl = make_desc(stage + OFF_ALO);
                    const uint64_t bdh = make_desc(stage + OFF_BHI);
                    const uint64_t bdl = make_desc(stage + OFF_BLO);
                    uint32_t en = (i != 0) ? 1u : 0u;
#pragma unroll
                    for (int kk = 0; kk < 4; ++kk) { mma_ss_cg2(tmem, adh + kk*2, bdh + kk*2, MMA_IDESC, en); en = 1; }
#pragma unroll
                    for (int kk = 0; kk < 4; ++kk) mma_ss_cg2(tmem, adh + kk*2, bdl + kk*2, MMA_IDESC, 1);
#pragma unroll
                    for (int kk = 0; kk < 4; ++kk) mma_ss_cg2(tmem, adl + kk*2, bdh + kk*2, MMA_IDESC, 1);
                    tc_commit_mc_cg2(sb + MB_MMA(s), 0x3);   // arrive both CTAs
                }
            }
        } else {
            // ---- follower relay: local load-done -> leader's LD barrier ----
            for (int i = 0; i < nch; ++i) {
                const int s = i % NSTAGE;
                MBARRIER_WAIT_PARITY(sb + MB_LD(s), (i / NSTAGE) & 1);
                if (elect_one()) {
                    asm volatile("fence.proxy.async;" ::: "memory");
                    MBARRIER_ARRIVE_CLUSTER(sb + MB_LD(s), 0);
                }
            }
        }
        // both ranks: drain final MMA commits. Stage s's last chunk is the
        // largest i < nch with i % 3 == s; its use index is i/3.
#pragma unroll
        for (int s = 0; s < NSTAGE; ++s) {
            int last = nch - 1 - ((nch - 1 - s) % NSTAGE);
            if (last >= 0)
                MBARRIER_WAIT_PARITY(sb + MB_MMA(s), (last / NSTAGE) & 1);
        }
    }
    __syncthreads();
    tc_fence_after();

    // ---- epilogue: each CTA reads its own 128 rows x 256 cols of D ----
    if (MODE == 1) {
        bf16* sH = reinterpret_cast<bf16*>(smem);                 // [128][130]
        bf16* sL = sH + 128 * 130;
        if (tid < 128) {
#pragma unroll
            for (int c0 = 0; c0 < 128; c0 += 32) {
                uint32_t gr[32], ur[32];
                tc_ld32(gr, tmem + c0);
                tc_ld32(ur, tmem + 128 + c0);
                tc_wait_ld();
#pragma unroll
                for (int j = 0; j < 32; ++j) {
                    float g = __uint_as_float(gr[j]);
                    float u = __uint_as_float(ur[j]);
                    float h = g * u / (1.0f + __expf(-g));
                    bf16 hv = __float2bfloat16(h);
                    sH[tid * 130 + c0 + j] = hv;
                    sL[tid * 130 + c0 + j] = __float2bfloat16(h - __bfloat162float(hv));
                }
            }
        }
        __syncthreads();
        const size_t obase = (size_t)(mbx * BM) * ldout + (size_t)nb * 128;
#pragma unroll 4
        for (int u = tid; u < 128 * 64; u += NTHREADS) {
            int r = u >> 6, cu = u & 63;
            __nv_bfloat162 vh = *reinterpret_cast<__nv_bfloat162*>(&sH[r * 130 + cu * 2]);
            __nv_bfloat162 vl = *reinterpret_cast<__nv_bfloat162*>(&sL[r * 130 + cu * 2]);
            *reinterpret_cast<__nv_bfloat162*>(Hhi + obase + (size_t)r * ldout + cu * 2) = vh;
            *reinterpret_cast<__nv_bfloat162*>(Hlo + obase + (size_t)r * ldout + cu * 2) = vl;
        }
    } else {
        float* sC = reinterpret_cast<float*>(smem);               // [128][257]
        if (tid < 128) {
#pragma unroll
            for (int c0 = 0; c0 < 256; c0 += 32) {
                uint32_t dr[32];
                tc_ld32(dr, tmem + c0);
                tc_wait_ld();
#pragma unroll
                for (int j = 0; j < 32; ++j)
                    sC[tid * 257 + c0 + j] = __uint_as_float(dr[j]);
            }
        }
        __syncthreads();
        const size_t obase = (size_t)(mbx * BM) * ldout + (size_t)nb * 256;
#pragma unroll 4
        for (int u = tid; u < 128 * 256; u += NTHREADS) {
            int r = u >> 8, col = u & 255;
            Cout[obase + (size_t)r * ldout + col] = sC[r * 257 + col];
        }
    }
    __syncthreads();
    CLUSTER_SYNC();                       // peer MMAs fully drained on both sides
    if (wid == 0) {
        tc_relinquish_cg2();
        tc_dealloc_cg2(tmem, 256);
    }
    CLUSTER_SYNC();

#else
    // ---------------- SIMT fallback (plain sm_103 target) ----------------
    const size_t boff = (MODE == 1) ? (size_t)nb * 128 * K : (size_t)nb * 256 * K;
    const bf16* b0_hi = B_hi + boff;
    const bf16* b0_lo = B_lo + boff;
    const bf16* b1_hi = (MODE == 1) ? (B1_hi + boff) : (B_hi + boff + (size_t)128 * K);
    const bf16* b1_lo = (MODE == 1) ? (B1_lo + boff) : (B_lo + boff + (size_t)128 * K);

    float* fA  = reinterpret_cast<float*>(smem);          // [8][128]
    float* fB0 = fA  + 8 * 128;
    float* fB1 = fB0 + 8 * 128;

    const int tx = tid & 15;
    const int ty = tid >> 4;
    const int lr = tid >> 1;
    const int lc = (tid & 1) << 2;

    float acc0[8][8], acc1[8][8];
#pragma unroll
    for (int i = 0; i < 8; i++)
#pragma unroll
        for (int j = 0; j < 8; j++) { acc0[i][j] = 0.0f; acc1[i][j] = 0.0f; }

    for (int k0 = 0; k0 < K; k0 += 8) {
        __syncthreads();
#pragma unroll
        for (int c = 0; c < 4; ++c) {
            int k = k0 + lc + c;
            size_t off = (size_t)lr * K + k;
            fA [(lc + c) * 128 + lr] = __bfloat162float(a_hi[off]) + __bfloat162float(a_lo[off]);
            fB0[(lc + c) * 128 + lr] = __bfloat162float(b0_hi[off]) + __bfloat162float(b0_lo[off]);
            fB1[(lc + c) * 128 + lr] = __bfloat162float(b1_hi[off]) + __bfloat162float(b1_lo[off]);
        }
        __syncthreads();
#pragma unroll
        for (int k = 0; k < 8; k++) {
            float ra[8], rb0[8], rb1[8];
#pragma unroll
            for (int i = 0; i < 8; i++) ra[i]  = fA [k * 128 + ty * 8 + i];
#pragma unroll
            for (int j = 0; j < 8; j++) { rb0[j] = fB0[k * 128 + tx * 8 + j]; rb1[j] = fB1[k * 128 + tx * 8 + j]; }
#pragma unroll
            for (int i = 0; i < 8; i++)
#pragma unroll
                for (int j = 0; j < 8; j++) {
                    acc0[i][j] = fmaf(ra[i], rb0[j], acc0[i][j]);
                    acc1[i][j] = fmaf(ra[i], rb1[j], acc1[i][j]);
                }
        }
    }

    if (MODE == 1) {
#pragma unroll
        for (int i = 0; i < 8; i++) {
            int m = mbx * BM + ty * 8 + i;
            bf16* hh = Hhi + (size_t)m * ldout + (size_t)nb * 128 + tx * 8;
            bf16* hl = Hlo + (size_t)m * ldout + (size_t)nb * 128 + tx * 8;
#pragma unroll
            for (int j = 0; j < 8; j++) {
                float g = acc0[i][j], u = acc1[i][j];
                float h = g * u / (1.0f + __expf(-g));
                bf16 hv = __float2bfloat16(h);
                hh[j] = hv;
                hl[j] = __float2bfloat16(h - __bfloat162float(hv));
            }
        }
    } else {
#pragma unroll
        for (int i = 0; i < 8; i++) {
            int m = mbx * BM + ty * 8 + i;
            float* co = Cout + (size_t)m * ldout + (size_t)nb * 256 + tx * 8;
#pragma unroll
            for (int j = 0; j < 8; j++) { co[j] = acc0[i][j]; co[128 + j] = acc1[i][j]; }
        }
    }
#endif
}

// ======================= fp32 -> bf16 hi/lo split =======================
__global__ void split_kernel(const float4* __restrict__ src,
                             __nv_bfloat162* __restrict__ hi,
                             __nv_bfloat162* __restrict__ lo, long n4)
{
    long i = (long)blockIdx.x * blockDim.x + threadIdx.x;
    if (i >= n4) return;
    float4 v = src[i];
    bf16 h0 = __float2bfloat16(v.x);
    bf16 h1 = __float2bfloat16(v.y);
    bf16 h2 = __float2bfloat16(v.z);
    bf16 h3 = __float2bfloat16(v.w);
    bf16 l0 = __float2bfloat16(v.x - __bfloat162float(h0));
    bf16 l1 = __float2bfloat16(v.y - __bfloat162float(h1));
    bf16 l2 = __float2bfloat16(v.z - __bfloat162float(h2));
    bf16 l3 = __float2bfloat16(v.w - __bfloat162float(h3));
    hi[2*i]   = __halves2bfloat162(h0, h1);
    hi[2*i+1] = __halves2bfloat162(h2, h3);
    lo[2*i]   = __halves2bfloat162(l0, l1);
    lo[2*i+1] = __halves2bfloat162(l2, l3);
}

// ======================= launch =======================
extern "C" void kernel_launch(void* const* d_in, const int* in_sizes, int n_in,
                              void* d_out, int out_size)
{
    const float* x   = (const float*)d_in[0];
    const float* wgu = (const float*)d_in[1];
    const float* wd  = (const float*)d_in[2];
    float* out       = (float*)d_out;

    bf16 *x_hi, *x_lo, *wgu_hi, *wgu_lo, *wd_hi, *wd_lo, *h_hi, *h_lo;
    cudaGetSymbolAddress((void**)&x_hi,  g_x_hi);
    cudaGetSymbolAddress((void**)&x_lo,  g_x_lo);
    cudaGetSymbolAddress((void**)&wgu_hi, g_wgu_hi);
    cudaGetSymbolAddress((void**)&wgu_lo, g_wgu_lo);
    cudaGetSymbolAddress((void**)&wd_hi, g_wd_hi);
    cudaGetSymbolAddress((void**)&wd_lo, g_wd_lo);
    cudaGetSymbolAddress((void**)&h_hi,  g_h_hi);
    cudaGetSymbolAddress((void**)&h_lo,  g_h_lo);

    cudaFuncSetAttribute(mlp_gemm<0>, cudaFuncAttributeMaxDynamicSharedMemorySize, SMEM_TOTAL);
    cudaFuncSetAttribute(mlp_gemm<1>, cudaFuncAttributeMaxDynamicSharedMemorySize, SMEM_TOTAL);

    // split inputs into bf16 hi/lo
    {
        long n4 = (long)M_DIM * H_DIM / 4;
        split_kernel<<<(unsigned)((n4 + 255) / 256), 256>>>(
            (const float4*)x, (__nv_bfloat162*)x_hi, (__nv_bfloat162*)x_lo, n4);
    }
    {
        long n4 = (long)2 * I_DIM * H_DIM / 4;
        split_kernel<<<(unsigned)((n4 + 255) / 256), 256>>>(
            (const float4*)wgu, (__nv_bfloat162*)wgu_hi, (__nv_bfloat162*)wgu_lo, n4);
    }
    {
        long n4 = (long)H_DIM * I_DIM / 4;
        split_kernel<<<(unsigned)((n4 + 255) / 256), 256>>>(
            (const float4*)wd, (__nv_bfloat162*)wd_hi, (__nv_bfloat162*)wd_lo, n4);
    }

    // GEMM1 (fused SwiGLU + h split): grid (M/128, I/128), clusters of 2 along x
    mlp_gemm<1><<<dim3(M_DIM / BM, I_DIM / 128), NTHREADS, SMEM_TOTAL>>>(
        x_hi, x_lo,
        wgu_hi, wgu_lo,
        wgu_hi + (size_t)I_DIM * H_DIM, wgu_lo + (size_t)I_DIM * H_DIM,
        H_DIM, I_DIM,
        nullptr, h_hi, h_lo);

    // GEMM2: out = h @ Wd^T: grid (M/128, H/256), clusters of 2 along x
    mlp_gemm<0><<<dim3(M_DIM / BM, H_DIM / 256), NTHREADS, SMEM_TOTAL>>>(
        h_hi, h_lo,
        wd_hi, wd_lo,
        nullptr, nullptr,
        I_DIM, H_DIM,
        out, nullptr, nullptr);
}

// round 8
// speedup vs baseline: 1.5710x; 1.3812x over previous
#include <cuda_runtime.h>
#include <cuda_bf16.h>
#include <cstdint>
#include <math.h>

typedef __nv_bfloat16 bf16;

// ---- arch gate: tcgen05 only exists on arch-specific (sm_103a) targets ----
#if defined(__CUDA_ARCH__) && ( \
      defined(__CUDA_ARCH_FEAT_SM103_ALL) || \
      defined(__CUDA_ARCH_FEAT_SM100_ALL) || \
      (defined(__CUDA_ARCH_SPECIFIC__) && (__CUDA_ARCH_SPECIFIC__ == 1030 || __CUDA_ARCH_SPECIFIC__ == 1000)) )
#define HAS_TC 1
#else
#define HAS_TC 0
#endif

// ---- problem dims ----
#define M_DIM 4096
#define H_DIM 4096
#define I_DIM 11008

// ---- GEMM tile config: cg2 pair computes M=256 x N=256 ----
#define BM 128          // per CTA
#define KC 64           // bf16 elems per K-chunk -> 128B rows (SW128 atom)
#define NTHREADS 256
#define NSTAGE 3

// ---- smem stage layout (bytes): A hi/lo [128x64], B-half hi/lo [128x64] ----
#define OFF_AHI 0
#define OFF_ALO (16*1024)
#define OFF_BHI (32*1024)
#define OFF_BLO (48*1024)
#define STAGE_BYTES (64*1024)
#define SMEM_STAGE0 1024
#define SMEM_TOTAL (SMEM_STAGE0 + NSTAGE*STAGE_BYTES)   // 197632 B

// mbarrier offsets: MMA[s] at 8+8s, LD[s] at 40+8s
#define MB_MMA(s) (8  + (s)*8)
#define MB_LD(s)  (40 + (s)*8)

// idesc: kind::f16, dtype=F32(1<<4), atype=BF16(1<<7), btype=BF16(1<<10),
// N=256 -> (256/8)<<17, M=256 (pair total) -> (256/16)<<24
#define MMA_IDESC ((1u<<4)|(1u<<7)|(1u<<10)|((256/8)<<17)|((256/16)<<24))

// SW128 K-major smem descriptor base (layout=2, version=1, SBO=64, LBO=1)
#define SMEM_DESC_BASE_SW128 \
    ((uint64_t(2) << 61) | (uint64_t(1) << 46) | (uint64_t(64) << 32) | (uint64_t(1) << 16))

// ---- device scratch (allocation-free rule) ----
__device__ bf16 g_x_hi [(size_t)M_DIM * H_DIM];
__device__ bf16 g_x_lo [(size_t)M_DIM * H_DIM];
__device__ bf16 g_wgu_hi[(size_t)2 * I_DIM * H_DIM];
__device__ bf16 g_wgu_lo[(size_t)2 * I_DIM * H_DIM];
__device__ bf16 g_wd_hi [(size_t)H_DIM * I_DIM];
__device__ bf16 g_wd_lo [(size_t)H_DIM * I_DIM];
__device__ bf16 g_h_hi  [(size_t)M_DIM * I_DIM];
__device__ bf16 g_h_lo  [(size_t)M_DIM * I_DIM];

// ======================= generic PTX helpers =======================

__device__ __forceinline__ uint32_t smem_u32(const void* p) {
    uint32_t a;
    asm("{ .reg .u64 t; cvta.to.shared.u64 t, %1; cvt.u32.u64 %0, t; }" : "=r"(a) : "l"(p));
    return a;
}

__device__ __forceinline__ uint32_t cluster_rank() {
    uint32_t r;
    asm("mov.u32 %0, %%cluster_ctarank;" : "=r"(r));
    return r;
}

__device__ __forceinline__ uint32_t elect_one() {
    uint32_t pred;
    asm volatile("{\n\t.reg .pred p;\n\telect.sync _|p, 0xFFFFFFFF;\n\tselp.b32 %0, 1, 0, p;\n\t}" : "=r"(pred));
    return pred;
}

__device__ __forceinline__ uint32_t swz(uint32_t off) { return off ^ ((off >> 3) & 0x70); }

__device__ __forceinline__ void cp16(uint32_t dst, const void* src) {
    asm volatile("cp.async.cg.shared.global [%0], [%1], 16;" :: "r"(dst), "l"(src) : "memory");
}

// .noinc REQUIRED (default form pre-increments pending count, self-cancelling)
__device__ __forceinline__ void cp_arrive(uint32_t mbar) {
    asm volatile("cp.async.mbarrier.arrive.noinc.shared::cta.b64 [%0];" :: "r"(mbar) : "memory");
}

// CHEAP, LOCAL async-proxy fence. The unscoped fence.proxy.async used in
// R6/R7 ordered against ALL outstanding async ops (incl. in-flight stage
// prefetches) and re-serialized the pipeline -> tensor pinned at ~48%.
__device__ __forceinline__ void fence_async_cta() {
    asm volatile("fence.proxy.async.shared::cta;" ::: "memory");
}

__device__ __forceinline__ uint64_t make_desc(uint32_t addr) {
    return SMEM_DESC_BASE_SW128 | ((uint64_t)(addr >> 4) & 0x3FFF);
}

#define MBARRIER_INIT(mbar, count) \
    asm volatile("mbarrier.init.shared.b64 [%0], %1;" \
        :: "r"((uint32_t)(mbar)), "r"((uint32_t)(count)) : "memory")

// arrive on the same-offset barrier in cluster CTA target_rank
#define MBARRIER_ARRIVE_CLUSTER(local_mbar_addr, target_rank) \
    asm volatile( \
        "{\n\t.reg .b32 remAddr32;\n\t" \
        "mapa.shared::cluster.u32 remAddr32, %0, %1;\n\t" \
        "mbarrier.arrive.release.cluster.shared::cluster.b64 _, [remAddr32];\n\t}" \
        :: "r"((uint32_t)(local_mbar_addr)), "r"((uint32_t)(target_rank)) : "memory")

#define MBARRIER_WAIT_PARITY(mbar_addr, phase_parity) do { \
    uint32_t _mbar = (uint32_t)(mbar_addr); \
    uint32_t _parity = (uint32_t)(phase_parity); \
    uint32_t _done; \
    asm volatile( \
        "{\n\t.reg .pred p;\n\t" \
        "mbarrier.try_wait.parity.acquire.cta.shared::cta.b64 p, [%1], %2;\n\t" \
        "selp.b32 %0, 1, 0, p;\n\t}" \
        : "=r"(_done) : "r"(_mbar), "r"(_parity) : "memory"); \
    if (!_done) { \
        asm volatile( \
            "{\n\t.reg .pred P1;\n\t" \
            "WAIT_LOOP_%=:\n\t" \
            "mbarrier.try_wait.parity.acquire.cta.shared::cta.b64 P1, [%0], %1, 0x989680;\n\t" \
            "@P1 bra.uni WAIT_DONE_%=;\n\t" \
            "bra.uni WAIT_LOOP_%=;\n\t" \
            "WAIT_DONE_%=:\n\t}" \
            :: "r"(_mbar), "r"(_parity) : "memory"); \
    } \
} while (0)

#define CLUSTER_SYNC() do { \
    asm volatile("barrier.cluster.arrive.aligned;" ::: "memory"); \
    asm volatile("barrier.cluster.wait.aligned;" ::: "memory"); \
} while (0)

// ======================= tcgen05 cg2 helpers =======================

__device__ __forceinline__ void mma_ss_cg2(uint32_t d, uint64_t ad, uint64_t bd,
                                           uint32_t idesc, uint32_t en) {
    asm volatile(
        "{\n\t"
        ".reg .pred p;\n\t"
        "setp.ne.u32 p, %4, 0;\n\t"
        "tcgen05.mma.cta_group::2.kind::f16 [%0], %1, %2, %3, {%5, %5, %5, %5, %5, %5, %5, %5}, p;\n\t"
        "}"
        :: "r"(d), "l"(ad), "l"(bd), "r"(idesc), "r"(en), "r"(0u)
        : "memory");
}

__device__ __forceinline__ void tc_alloc_cg2(uint32_t smem_result_addr, uint32_t nCols) {
    asm volatile("tcgen05.alloc.cta_group::2.sync.aligned.shared::cta.b32 [%0], %1;"
        :: "r"(smem_result_addr), "r"(nCols) : "memory");
}
__device__ __forceinline__ void tc_dealloc_cg2(uint32_t tmem_addr, uint32_t nCols) {
    asm volatile("tcgen05.dealloc.cta_group::2.sync.aligned.b32 %0, %1;"
        :: "r"(tmem_addr), "r"(nCols));
}
__device__ __forceinline__ void tc_relinquish_cg2() {
    asm volatile("tcgen05.relinquish_alloc_permit.cta_group::2.sync.aligned;");
}
__device__ __forceinline__ void tc_commit_mc_cg2(uint32_t mbar, uint16_t mask) {
    asm volatile("tcgen05.commit.cta_group::2.mbarrier::arrive::one.shared::cluster.multicast::cluster.b64 [%0], %1;"
        :: "r"(mbar), "h"(mask) : "memory");
}
__device__ __forceinline__ void tc_fence_after() {
    asm volatile("tcgen05.fence::after_thread_sync;" ::: "memory");
}
__device__ __forceinline__ void tc_wait_ld() {
    asm volatile("tcgen05.wait::ld.sync.aligned;" ::: "memory");
}
__device__ __forceinline__ void tc_ld32(uint32_t* r, uint32_t tmem_addr) {
    asm volatile(
        "tcgen05.ld.sync.aligned.32x32b.x32.b32 "
        "{%0, %1, %2, %3, %4, %5, %6, %7, "
        " %8, %9, %10, %11, %12, %13, %14, %15, "
        " %16, %17, %18, %19, %20, %21, %22, %23, "
        " %24, %25, %26, %27, %28, %29, %30, %31}, [%32];"
        : "=r"(r[0]),  "=r"(r[1]),  "=r"(r[2]),  "=r"(r[3]),
          "=r"(r[4]),  "=r"(r[5]),  "=r"(r[6]),  "=r"(r[7]),
          "=r"(r[8]),  "=r"(r[9]),  "=r"(r[10]), "=r"(r[11]),
          "=r"(r[12]), "=r"(r[13]), "=r"(r[14]), "=r"(r[15]),
          "=r"(r[16]), "=r"(r[17]), "=r"(r[18]), "=r"(r[19]),
          "=r"(r[20]), "=r"(r[21]), "=r"(r[22]), "=r"(r[23]),
          "=r"(r[24]), "=r"(r[25]), "=r"(r[26]), "=r"(r[27]),
          "=r"(r[28]), "=r"(r[29]), "=r"(r[30]), "=r"(r[31])
        : "r"(tmem_addr));
}

// ======================= tile loader (128 loader threads) =======================
// Per CTA per chunk: A hi/lo [128x64 bf16] + B-half hi/lo [128x64 bf16]
// = 4096 x 16B units / 128 threads = 32 cp16 each (8 per tensor).
__device__ __forceinline__ void load_chunk128(
    uint32_t sbase, int t, int k0, int K,
    const bf16* a_hi, const bf16* a_lo,
    const bf16* bh_hi, const bf16* bh_lo)
{
#pragma unroll
    for (int j = 0; j < 8; ++j) {
        int cc = t + j * 128, row = cc >> 3, col = cc & 7;
        cp16(sbase + OFF_AHI + swz((uint32_t)row * 128 + col * 16),
             a_hi + (size_t)row * K + k0 + col * 8);
    }
#pragma unroll
    for (int j = 0; j < 8; ++j) {
        int cc = t + j * 128, row = cc >> 3, col = cc & 7;
        cp16(sbase + OFF_ALO + swz((uint32_t)row * 128 + col * 16),
             a_lo + (size_t)row * K + k0 + col * 8);
    }
#pragma unroll
    for (int j = 0; j < 8; ++j) {
        int cc = t + j * 128, row = cc >> 3, col = cc & 7;
        cp16(sbase + OFF_BHI + swz((uint32_t)row * 128 + col * 16),
             bh_hi + (size_t)row * K + k0 + col * 8);
    }
#pragma unroll
    for (int j = 0; j < 8; ++j) {
        int cc = t + j * 128, row = cc >> 3, col = cc & 7;
        cp16(sbase + OFF_BLO + swz((uint32_t)row * 128 + col * 16),
             bh_lo + (size_t)row * K + k0 + col * 8);
    }
}

// ======================= fused GEMM (cg2 pair, 3-stage ring) =======================
// Pair = 2 CTAs along blockIdx.x (cluster (2,1,1)); rank r owns M rows mbx*128.
// MODE 1: gu slice; B rank0 = gate rows, rank1 = up rows (N=256 = [gate|up]);
//         epilogue SwiGLU -> h hi/lo.  grid (M/128, I/128).
// MODE 0: out = h @ Wd^T; rank r holds B rows nb*256 + r*128.  grid (M/128, H/256).
template<int MODE>
__global__ void __launch_bounds__(NTHREADS, 1) __cluster_dims__(2, 1, 1)
mlp_gemm(const bf16* __restrict__ A_hi, const bf16* __restrict__ A_lo,
         const bf16* __restrict__ B_hi, const bf16* __restrict__ B_lo,
         const bf16* __restrict__ B1_hi, const bf16* __restrict__ B1_lo,
         int K, int ldout,
         float* __restrict__ Cout,
         bf16* __restrict__ Hhi, bf16* __restrict__ Hlo)
{
    extern __shared__ __align__(1024) char smem[];
    const int tid = threadIdx.x;
    const int mbx = blockIdx.x, nb = blockIdx.y;

    const bf16* a_hi = A_hi + (size_t)mbx * BM * K;
    const bf16* a_lo = A_lo + (size_t)mbx * BM * K;

#if HAS_TC
    // ---------------- cg2 tcgen05 warp-specialized path ----------------
    const uint32_t sb = smem_u32(smem);
    const int wid = tid >> 5;
    const uint32_t rank = cluster_rank();

    // B half for this rank (128 rows)
    const bf16 *bh_hi, *bh_lo;
    if (MODE == 1) {
        size_t o = (size_t)nb * 128 * K;
        bh_hi = (rank ? B1_hi : B_hi) + o;
        bh_lo = (rank ? B1_lo : B_lo) + o;
    } else {
        size_t o = ((size_t)nb * 256 + rank * 128) * K;
        bh_hi = B_hi + o;
        bh_lo = B_lo + o;
    }

    if (wid == 0) tc_alloc_cg2(sb + 0, 256);
    if (tid == 0) {
        const uint32_t ldc = (rank == 0) ? 129u : 128u;   // +1 remote relay on leader
#pragma unroll
        for (int s = 0; s < NSTAGE; ++s) {
            MBARRIER_INIT(sb + MB_MMA(s), 1);
            MBARRIER_INIT(sb + MB_LD(s), ldc);
        }
    }
    __syncthreads();
    uint32_t tmem;
    asm volatile("ld.shared.b32 %0, [%1];" : "=r"(tmem) : "r"(sb));

    // all mbarriers initialized in both CTAs before any cross-CTA traffic
    CLUSTER_SYNC();

    const int nch = K / KC;          // 64 (GEMM1) / 172 (GEMM2)

    if (wid >= 4) {
        // ---- loader warps: 128 threads, local A + local B-half ----
        const int t = tid - 128;
        for (int i = 0; i < nch; ++i) {
            const int s = i % NSTAGE;
            if (i >= NSTAGE) {
                // buffer s last used by chunk i-3 (use index i/3 - 1)
                MBARRIER_WAIT_PARITY(sb + MB_MMA(s), ((i / NSTAGE) - 1) & 1);
            }
            load_chunk128(sb + SMEM_STAGE0 + (uint32_t)s * STAGE_BYTES, t, i * KC, K,
                          a_hi, a_lo, bh_hi, bh_lo);
            cp_arrive(sb + MB_LD(s));
        }
    } else if (wid == 0) {
        if (rank == 0) {
            // ---- leader: issue cg2 MMAs; never waits for MMA completion ----
            for (int i = 0; i < nch; ++i) {
                const int s = i % NSTAGE;
                MBARRIER_WAIT_PARITY(sb + MB_LD(s), (i / NSTAGE) & 1);
                if (elect_one()) {
                    fence_async_cta();               // LOCAL scope (the R7 bug fix)
                    const uint32_t stage = sb + SMEM_STAGE0 + (uint32_t)s * STAGE_BYTES;
                    const uint64_t adh = make_desc(stage + OFF_AHI);
                    const uint64_t adl = make_desc(stage + OFF_ALO);
                    const uint64_t bdh = make_desc(stage + OFF_BHI);
                    const uint64_t bdl = make_desc(stage + OFF_BLO);
                    uint32_t en = (i != 0) ? 1u : 0u;
#pragma unroll
                    for (int kk = 0; kk < 4; ++kk) { mma_ss_cg2(tmem, adh + kk*2, bdh + kk*2, MMA_IDESC, en); en = 1; }
#pragma unroll
                    for (int kk = 0; kk < 4; ++kk) mma_ss_cg2(tmem, adh + kk*2, bdl + kk*2, MMA_IDESC, 1);
#pragma unroll
                    for (int kk = 0; kk < 4; ++kk) mma_ss_cg2(tmem, adl + kk*2, bdh + kk*2, MMA_IDESC, 1);
                    tc_commit_mc_cg2(sb + MB_MMA(s), 0x3);   // arrive both CTAs
                }
            }
        } else {
            // ---- follower relay: local load-done -> leader's LD barrier ----
            for (int i = 0; i < nch; ++i) {
                const int s = i % NSTAGE;
                MBARRIER_WAIT_PARITY(sb + MB_LD(s), (i / NSTAGE) & 1);
                if (elect_one()) {
                    fence_async_cta();               // LOCAL scope (the R7 bug fix)
                    MBARRIER_ARRIVE_CLUSTER(sb + MB_LD(s), 0);
                }
            }
        }
        // both ranks: drain final MMA commits. Stage s's last chunk is the
        // largest i < nch with i % 3 == s; its use index is i/3.
#pragma unroll
        for (int s = 0; s < NSTAGE; ++s) {
            int last = nch - 1 - ((nch - 1 - s) % NSTAGE);
            if (last >= 0)
                MBARRIER_WAIT_PARITY(sb + MB_MMA(s), (last / NSTAGE) & 1);
        }
    }
    __syncthreads();
    tc_fence_after();

    // ---- epilogue: each CTA reads its own 128 rows x 256 cols of D ----
    if (MODE == 1) {
        bf16* sH = reinterpret_cast<bf16*>(smem);                 // [128][130]
        bf16* sL = sH + 128 * 130;
        if (tid < 128) {
#pragma unroll
            for (int c0 = 0; c0 < 128; c0 += 32) {
                uint32_t gr[32], ur[32];
                tc_ld32(gr, tmem + c0);
                tc_ld32(ur, tmem + 128 + c0);
                tc_wait_ld();
#pragma unroll
                for (int j = 0; j < 32; ++j) {
                    float g = __uint_as_float(gr[j]);
                    float u = __uint_as_float(ur[j]);
                    float h = g * u / (1.0f + __expf(-g));
                    bf16 hv = __float2bfloat16(h);
                    sH[tid * 130 + c0 + j] = hv;
                    sL[tid * 130 + c0 + j] = __float2bfloat16(h - __bfloat162float(hv));
                }
            }
        }
        __syncthreads();
        const size_t obase = (size_t)(mbx * BM) * ldout + (size_t)nb * 128;
#pragma unroll 4
        for (int u = tid; u < 128 * 64; u += NTHREADS) {
            int r = u >> 6, cu = u & 63;
            __nv_bfloat162 vh = *reinterpret_cast<__nv_bfloat162*>(&sH[r * 130 + cu * 2]);
            __nv_bfloat162 vl = *reinterpret_cast<__nv_bfloat162*>(&sL[r * 130 + cu * 2]);
            *reinterpret_cast<__nv_bfloat162*>(Hhi + obase + (size_t)r * ldout + cu * 2) = vh;
            *reinterpret_cast<__nv_bfloat162*>(Hlo + obase + (size_t)r * ldout + cu * 2) = vl;
        }
    } else {
        float* sC = reinterpret_cast<float*>(smem);               // [128][257]
        if (tid < 128) {
#pragma unroll
            for (int c0 = 0; c0 < 256; c0 += 32) {
                uint32_t dr[32];
                tc_ld32(dr, tmem + c0);
                tc_wait_ld();
#pragma unroll
                for (int j = 0; j < 32; ++j)
                    sC[tid * 257 + c0 + j] = __uint_as_float(dr[j]);
            }
        }
        __syncthreads();
        const size_t obase = (size_t)(mbx * BM) * ldout + (size_t)nb * 256;
#pragma unroll 4
        for (int u = tid; u < 128 * 256; u += NTHREADS) {
            int r = u >> 8, col = u & 255;
            Cout[obase + (size_t)r * ldout + col] = sC[r * 257 + col];
        }
    }
    __syncthreads();
    CLUSTER_SYNC();                       // peer MMAs fully drained on both sides
    if (wid == 0) {
        tc_relinquish_cg2();
        tc_dealloc_cg2(tmem, 256);
    }
    CLUSTER_SYNC();

#else
    // ---------------- SIMT fallback (plain sm_103 target) ----------------
    const size_t boff = (MODE == 1) ? (size_t)nb * 128 * K : (size_t)nb * 256 * K;
    const bf16* b0_hi = B_hi + boff;
    const bf16* b0_lo = B_lo + boff;
    const bf16* b1_hi = (MODE == 1) ? (B1_hi + boff) : (B_hi + boff + (size_t)128 * K);
    const bf16* b1_lo = (MODE == 1) ? (B1_lo + boff) : (B_lo + boff + (size_t)128 * K);

    float* fA  = reinterpret_cast<float*>(smem);          // [8][128]
    float* fB0 = fA  + 8 * 128;
    float* fB1 = fB0 + 8 * 128;

    const int tx = tid & 15;
    const int ty = tid >> 4;
    const int lr = tid >> 1;
    const int lc = (tid & 1) << 2;

    float acc0[8][8], acc1[8][8];
#pragma unroll
    for (int i = 0; i < 8; i++)
#pragma unroll
        for (int j = 0; j < 8; j++) { acc0[i][j] = 0.0f; acc1[i][j] = 0.0f; }

    for (int k0 = 0; k0 < K; k0 += 8) {
        __syncthreads();
#pragma unroll
        for (int c = 0; c < 4; ++c) {
            int k = k0 + lc + c;
            size_t off = (size_t)lr * K + k;
            fA [(lc + c) * 128 + lr] = __bfloat162float(a_hi[off]) + __bfloat162float(a_lo[off]);
            fB0[(lc + c) * 128 + lr] = __bfloat162float(b0_hi[off]) + __bfloat162float(b0_lo[off]);
            fB1[(lc + c) * 128 + lr] = __bfloat162float(b1_hi[off]) + __bfloat162float(b1_lo[off]);
        }
        __syncthreads();
#pragma unroll
        for (int k = 0; k < 8; k++) {
            float ra[8], rb0[8], rb1[8];
#pragma unroll
            for (int i = 0; i < 8; i++) ra[i]  = fA [k * 128 + ty * 8 + i];
#pragma unroll
            for (int j = 0; j < 8; j++) { rb0[j] = fB0[k * 128 + tx * 8 + j]; rb1[j] = fB1[k * 128 + tx * 8 + j]; }
#pragma unroll
            for (int i = 0; i < 8; i++)
#pragma unroll
                for (int j = 0; j < 8; j++) {
                    acc0[i][j] = fmaf(ra[i], rb0[j], acc0[i][j]);
                    acc1[i][j] = fmaf(ra[i], rb1[j], acc1[i][j]);
                }
        }
    }

    if (MODE == 1) {
#pragma unroll
        for (int i = 0; i < 8; i++) {
            int m = mbx * BM + ty * 8 + i;
            bf16* hh = Hhi + (size_t)m * ldout + (size_t)nb * 128 + tx * 8;
            bf16* hl = Hlo + (size_t)m * ldout + (size_t)nb * 128 + tx * 8;
#pragma unroll
            for (int j = 0; j < 8; j++) {
                float g = acc0[i][j], u = acc1[i][j];
                float h = g * u / (1.0f + __expf(-g));
                bf16 hv = __float2bfloat16(h);
                hh[j] = hv;
                hl[j] = __float2bfloat16(h - __bfloat162float(hv));
            }
        }
    } else {
#pragma unroll
        for (int i = 0; i < 8; i++) {
            int m = mbx * BM + ty * 8 + i;
            float* co = Cout + (size_t)m * ldout + (size_t)nb * 256 + tx * 8;
#pragma unroll
            for (int j = 0; j < 8; j++) { co[j] = acc0[i][j]; co[128 + j] = acc1[i][j]; }
        }
    }
#endif
}

// ======================= fp32 -> bf16 hi/lo split =======================
__global__ void split_kernel(const float4* __restrict__ src,
                             __nv_bfloat162* __restrict__ hi,
                             __nv_bfloat162* __restrict__ lo, long n4)
{
    long i = (long)blockIdx.x * blockDim.x + threadIdx.x;
    if (i >= n4) return;
    float4 v = src[i];
    bf16 h0 = __float2bfloat16(v.x);
    bf16 h1 = __float2bfloat16(v.y);
    bf16 h2 = __float2bfloat16(v.z);
    bf16 h3 = __float2bfloat16(v.w);
    bf16 l0 = __float2bfloat16(v.x - __bfloat162float(h0));
    bf16 l1 = __float2bfloat16(v.y - __bfloat162float(h1));
    bf16 l2 = __float2bfloat16(v.z - __bfloat162float(h2));
    bf16 l3 = __float2bfloat16(v.w - __bfloat162float(h3));
    hi[2*i]   = __halves2bfloat162(h0, h1);
    hi[2*i+1] = __halves2bfloat162(h2, h3);
    lo[2*i]   = __halves2bfloat162(l0, l1);
    lo[2*i+1] = __halves2bfloat162(l2, l3);
}

// ======================= launch =======================
extern "C" void kernel_launch(void* const* d_in, const int* in_sizes, int n_in,
                              void* d_out, int out_size)
{
    const float* x   = (const float*)d_in[0];
    const float* wgu = (const float*)d_in[1];
    const float* wd  = (const float*)d_in[2];
    float* out       = (float*)d_out;

    bf16 *x_hi, *x_lo, *wgu_hi, *wgu_lo, *wd_hi, *wd_lo, *h_hi, *h_lo;
    cudaGetSymbolAddress((void**)&x_hi,  g_x_hi);
    cudaGetSymbolAddress((void**)&x_lo,  g_x_lo);
    cudaGetSymbolAddress((void**)&wgu_hi, g_wgu_hi);
    cudaGetSymbolAddress((void**)&wgu_lo, g_wgu_lo);
    cudaGetSymbolAddress((void**)&wd_hi, g_wd_hi);
    cudaGetSymbolAddress((void**)&wd_lo, g_wd_lo);
    cudaGetSymbolAddress((void**)&h_hi,  g_h_hi);
    cudaGetSymbolAddress((void**)&h_lo,  g_h_lo);

    cudaFuncSetAttribute(mlp_gemm<0>, cudaFuncAttributeMaxDynamicSharedMemorySize, SMEM_TOTAL);
    cudaFuncSetAttribute(mlp_gemm<1>, cudaFuncAttributeMaxDynamicSharedMemorySize, SMEM_TOTAL);

    // split inputs into bf16 hi/lo
    {
        long n4 = (long)M_DIM * H_DIM / 4;
        split_kernel<<<(unsigned)((n4 + 255) / 256), 256>>>(
            (const float4*)x, (__nv_bfloat162*)x_hi, (__nv_bfloat162*)x_lo, n4);
    }
    {
        long n4 = (long)2 * I_DIM * H_DIM / 4;
        split_kernel<<<(unsigned)((n4 + 255) / 256), 256>>>(
            (const float4*)wgu, (__nv_bfloat162*)wgu_hi, (__nv_bfloat162*)wgu_lo, n4);
    }
    {
        long n4 = (long)H_DIM * I_DIM / 4;
        split_kernel<<<(unsigned)((n4 + 255) / 256), 256>>>(
            (const float4*)wd, (__nv_bfloat162*)wd_hi, (__nv_bfloat162*)wd_lo, n4);
    }

    // GEMM1 (fused SwiGLU + h split): grid (M/128, I/128), clusters of 2 along x
    mlp_gemm<1><<<dim3(M_DIM / BM, I_DIM / 128), NTHREADS, SMEM_TOTAL>>>(
        x_hi, x_lo,
        wgu_hi, wgu_lo,
        wgu_hi + (size_t)I_DIM * H_DIM, wgu_lo + (size_t)I_DIM * H_DIM,
        H_DIM, I_DIM,
        nullptr, h_hi, h_lo);

    // GEMM2: out = h @ Wd^T: grid (M/128, H/256), clusters of 2 along x
    mlp_gemm<0><<<dim3(M_DIM / BM, H_DIM / 256), NTHREADS, SMEM_TOTAL>>>(
        h_hi, h_lo,
        wd_hi, wd_lo,
        nullptr, nullptr,
        I_DIM, H_DIM,
        out, nullptr, nullptr);
}

// round 9
// speedup vs baseline: 1.6990x; 1.0815x over previous
#include <cuda_runtime.h>
#include <cuda_bf16.h>
#include <cstdint>
#include <math.h>

typedef __nv_bfloat16 bf16;

// ---- arch gate: tcgen05 only exists on arch-specific (sm_103a) targets ----
#if defined(__CUDA_ARCH__) && ( \
      defined(__CUDA_ARCH_FEAT_SM103_ALL) || \
      defined(__CUDA_ARCH_FEAT_SM100_ALL) || \
      (defined(__CUDA_ARCH_SPECIFIC__) && (__CUDA_ARCH_SPECIFIC__ == 1030 || __CUDA_ARCH_SPECIFIC__ == 1000)) )
#define HAS_TC 1
#else
#define HAS_TC 0
#endif

// ---- problem dims ----
#define M_DIM 4096
#define H_DIM 4096
#define I_DIM 11008

// ---- tile config: cg2 pair computes M=256 x N=256, persistent clusters ----
#define BM 128          // per CTA
#define KC 64           // bf16 per K-chunk -> 128B rows (SW128 atom)
#define NTHREADS 384    // w0 MMA/relay, w4-7 loaders, w8-11 epilogue
#define NSTAGE 3
#define NCLUSTERS 74

// ---- smem stage layout (bytes): A hi/lo [128x64], B-half hi/lo [128x64] ----
#define OFF_AHI 0
#define OFF_ALO (16*1024)
#define OFF_BHI (32*1024)
#define OFF_BLO (48*1024)
#define STAGE_BYTES (64*1024)
#define SMEM_STAGE0 1024
#define SMEM_TOTAL (SMEM_STAGE0 + NSTAGE*STAGE_BYTES)   // 197632 B

// mbarrier offsets
#define MB_MMA(s)  (8  + (s)*8)     // 8,16,24   : leader's per-chunk commit (gates loaders)
#define MB_LD(s)   (40 + (s)*8)     // 40,48,56  : loads done (129 leader / 128 follower)
#define MB_TILE(b) (64 + (b)*8)     // 64,72     : tile's MMAs complete (gates epilogue)
#define MB_EPI(b)  (80 + (b)*8)     // 80,88     : epilogue done, buffer reusable (256 arrives, leader)

// idesc: kind::f16, F32 acc, BF16xBF16, N=256, M=256 (pair)
#define MMA_IDESC ((1u<<4)|(1u<<7)|(1u<<10)|((256/8)<<17)|((256/16)<<24))

// SW128 K-major smem descriptor base (layout=2, version=1, SBO=64, LBO=1)
#define SMEM_DESC_BASE_SW128 \
    ((uint64_t(2) << 61) | (uint64_t(1) << 46) | (uint64_t(64) << 32) | (uint64_t(1) << 16))

// ---- device scratch (allocation-free rule) ----
__device__ bf16 g_x_hi [(size_t)M_DIM * H_DIM];
__device__ bf16 g_x_lo [(size_t)M_DIM * H_DIM];
__device__ bf16 g_wgu_hi[(size_t)2 * I_DIM * H_DIM];
__device__ bf16 g_wgu_lo[(size_t)2 * I_DIM * H_DIM];
__device__ bf16 g_wd_hi [(size_t)H_DIM * I_DIM];
__device__ bf16 g_wd_lo [(size_t)H_DIM * I_DIM];
__device__ bf16 g_h_hi  [(size_t)M_DIM * I_DIM];
__device__ bf16 g_h_lo  [(size_t)M_DIM * I_DIM];

// ======================= generic PTX helpers =======================

__device__ __forceinline__ uint32_t smem_u32(const void* p) {
    uint32_t a;
    asm("{ .reg .u64 t; cvta.to.shared.u64 t, %1; cvt.u32.u64 %0, t; }" : "=r"(a) : "l"(p));
    return a;
}
__device__ __forceinline__ uint32_t cluster_rank() {
    uint32_t r;
    asm("mov.u32 %0, %%cluster_ctarank;" : "=r"(r));
    return r;
}
__device__ __forceinline__ uint32_t elect_one() {
    uint32_t pred;
    asm volatile("{\n\t.reg .pred p;\n\telect.sync _|p, 0xFFFFFFFF;\n\tselp.b32 %0, 1, 0, p;\n\t}" : "=r"(pred));
    return pred;
}
__device__ __forceinline__ uint32_t swz(uint32_t off) { return off ^ ((off >> 3) & 0x70); }

__device__ __forceinline__ void cp16(uint32_t dst, const void* src) {
    asm volatile("cp.async.cg.shared.global [%0], [%1], 16;" :: "r"(dst), "l"(src) : "memory");
}
// .noinc REQUIRED (default form pre-increments pending count, self-cancelling)
__device__ __forceinline__ void cp_arrive(uint32_t mbar) {
    asm volatile("cp.async.mbarrier.arrive.noinc.shared::cta.b64 [%0];" :: "r"(mbar) : "memory");
}
// LOCAL async-proxy fence (unscoped variant re-serializes in-flight prefetches)
__device__ __forceinline__ void fence_async_cta() {
    asm volatile("fence.proxy.async.shared::cta;" ::: "memory");
}
__device__ __forceinline__ uint64_t make_desc(uint32_t addr) {
    return SMEM_DESC_BASE_SW128 | ((uint64_t)(addr >> 4) & 0x3FFF);
}

#define MBARRIER_INIT(mbar, count) \
    asm volatile("mbarrier.init.shared.b64 [%0], %1;" \
        :: "r"((uint32_t)(mbar)), "r"((uint32_t)(count)) : "memory")

#define MBARRIER_ARRIVE_LOCAL(mbar) \
    asm volatile("mbarrier.arrive.release.cta.shared::cta.b64 _, [%0];" \
        :: "r"((uint32_t)(mbar)) : "memory")

#define MBARRIER_ARRIVE_CLUSTER(local_mbar_addr, target_rank) \
    asm volatile( \
        "{\n\t.reg .b32 remAddr32;\n\t" \
        "mapa.shared::cluster.u32 remAddr32, %0, %1;\n\t" \
        "mbarrier.arrive.release.cluster.shared::cluster.b64 _, [remAddr32];\n\t}" \
        :: "r"((uint32_t)(local_mbar_addr)), "r"((uint32_t)(target_rank)) : "memory")

#define MBARRIER_WAIT_PARITY(mbar_addr, phase_parity) do { \
    uint32_t _mbar = (uint32_t)(mbar_addr); \
    uint32_t _parity = (uint32_t)(phase_parity); \
    uint32_t _done; \
    asm volatile( \
        "{\n\t.reg .pred p;\n\t" \
        "mbarrier.try_wait.parity.acquire.cta.shared::cta.b64 p, [%1], %2;\n\t" \
        "selp.b32 %0, 1, 0, p;\n\t}" \
        : "=r"(_done) : "r"(_mbar), "r"(_parity) : "memory"); \
    if (!_done) { \
        asm volatile( \
            "{\n\t.reg .pred P1;\n\t" \
            "WAIT_LOOP_%=:\n\t" \
            "mbarrier.try_wait.parity.acquire.cta.shared::cta.b64 P1, [%0], %1, 0x989680;\n\t" \
            "@P1 bra.uni WAIT_DONE_%=;\n\t" \
            "bra.uni WAIT_LOOP_%=;\n\t" \
            "WAIT_DONE_%=:\n\t}" \
            :: "r"(_mbar), "r"(_parity) : "memory"); \
    } \
} while (0)

#define CLUSTER_SYNC() do { \
    asm volatile("barrier.cluster.arrive.aligned;" ::: "memory"); \
    asm volatile("barrier.cluster.wait.aligned;" ::: "memory"); \
} while (0)

// ======================= tcgen05 cg2 helpers =======================

__device__ __forceinline__ void mma_ss_cg2(uint32_t d, uint64_t ad, uint64_t bd,
                                           uint32_t idesc, uint32_t en) {
    asm volatile(
        "{\n\t"
        ".reg .pred p;\n\t"
        "setp.ne.u32 p, %4, 0;\n\t"
        "tcgen05.mma.cta_group::2.kind::f16 [%0], %1, %2, %3, {%5, %5, %5, %5, %5, %5, %5, %5}, p;\n\t"
        "}"
        :: "r"(d), "l"(ad), "l"(bd), "r"(idesc), "r"(en), "r"(0u)
        : "memory");
}
__device__ __forceinline__ void tc_alloc_cg2(uint32_t smem_result_addr, uint32_t nCols) {
    asm volatile("tcgen05.alloc.cta_group::2.sync.aligned.shared::cta.b32 [%0], %1;"
        :: "r"(smem_result_addr), "r"(nCols) : "memory");
}
__device__ __forceinline__ void tc_dealloc_cg2(uint32_t tmem_addr, uint32_t nCols) {
    asm volatile("tcgen05.dealloc.cta_group::2.sync.aligned.b32 %0, %1;"
        :: "r"(tmem_addr), "r"(nCols));
}
__device__ __forceinline__ void tc_relinquish_cg2() {
    asm volatile("tcgen05.relinquish_alloc_permit.cta_group::2.sync.aligned;");
}
__device__ __forceinline__ void tc_commit_mc_cg2(uint32_t mbar, uint16_t mask) {
    asm volatile("tcgen05.commit.cta_group::2.mbarrier::arrive::one.shared::cluster.multicast::cluster.b64 [%0], %1;"
        :: "r"(mbar), "h"(mask) : "memory");
}
__device__ __forceinline__ void tc_fence_after() {
    asm volatile("tcgen05.fence::after_thread_sync;" ::: "memory");
}
__device__ __forceinline__ void tc_fence_before() {
    asm volatile("tcgen05.fence::before_thread_sync;" ::: "memory");
}
__device__ __forceinline__ void tc_wait_ld() {
    asm volatile("tcgen05.wait::ld.sync.aligned;" ::: "memory");
}
__device__ __forceinline__ void tc_ld32(uint32_t* r, uint32_t tmem_addr) {
    asm volatile(
        "tcgen05.ld.sync.aligned.32x32b.x32.b32 "
        "{%0, %1, %2, %3, %4, %5, %6, %7, "
        " %8, %9, %10, %11, %12, %13, %14, %15, "
        " %16, %17, %18, %19, %20, %21, %22, %23, "
        " %24, %25, %26, %27, %28, %29, %30, %31}, [%32];"
        : "=r"(r[0]),  "=r"(r[1]),  "=r"(r[2]),  "=r"(r[3]),
          "=r"(r[4]),  "=r"(r[5]),  "=r"(r[6]),  "=r"(r[7]),
          "=r"(r[8]),  "=r"(r[9]),  "=r"(r[10]), "=r"(r[11]),
          "=r"(r[12]), "=r"(r[13]), "=r"(r[14]), "=r"(r[15]),
          "=r"(r[16]), "=r"(r[17]), "=r"(r[18]), "=r"(r[19]),
          "=r"(r[20]), "=r"(r[21]), "=r"(r[22]), "=r"(r[23]),
          "=r"(r[24]), "=r"(r[25]), "=r"(r[26]), "=r"(r[27]),
          "=r"(r[28]), "=r"(r[29]), "=r"(r[30]), "=r"(r[31])
        : "r"(tmem_addr));
}

// ======================= tile loader (128 loader threads) =======================
__device__ __forceinline__ void load_chunk128(
    uint32_t sbase, int t, int k0, int K,
    const bf16* a_hi, const bf16* a_lo,
    const bf16* bh_hi, const bf16* bh_lo)
{
#pragma unroll
    for (int j = 0; j < 8; ++j) {
        int cc = t + j * 128, row = cc >> 3, col = cc & 7;
        cp16(sbase + OFF_AHI + swz((uint32_t)row * 128 + col * 16),
             a_hi + (size_t)row * K + k0 + col * 8);
    }
#pragma unroll
    for (int j = 0; j < 8; ++j) {
        int cc = t + j * 128, row = cc >> 3, col = cc & 7;
        cp16(sbase + OFF_ALO + swz((uint32_t)row * 128 + col * 16),
             a_lo + (size_t)row * K + k0 + col * 8);
    }
#pragma unroll
    for (int j = 0; j < 8; ++j) {
        int cc = t + j * 128, row = cc >> 3, col = cc & 7;
        cp16(sbase + OFF_BHI + swz((uint32_t)row * 128 + col * 16),
             bh_hi + (size_t)row * K + k0 + col * 8);
    }
#pragma unroll
    for (int j = 0; j < 8; ++j) {
        int cc = t + j * 128, row = cc >> 3, col = cc & 7;
        cp16(sbase + OFF_BLO + swz((uint32_t)row * 128 + col * 16),
             bh_lo + (size_t)row * K + k0 + col * 8);
    }
}

// compute B-half pointers for a tile
template<int MODE>
__device__ __forceinline__ void tile_b_ptrs(
    int nb, uint32_t rank, int K,
    const bf16* B_hi, const bf16* B_lo,
    const bf16* B1_hi, const bf16* B1_lo,
    const bf16** bh_hi, const bf16** bh_lo)
{
    if (MODE == 1) {
        size_t o = (size_t)nb * 128 * K;
        *bh_hi = (rank ? B1_hi : B_hi) + o;
        *bh_lo = (rank ? B1_lo : B_lo) + o;
    } else {
        size_t o = ((size_t)nb * 256 + rank * 128) * K;
        *bh_hi = B_hi + o;
        *bh_lo = B_lo + o;
    }
}

// ======================= persistent fused GEMM (cg2, TMEM double-buffer) ===========
// grid (148,1,1), cluster (2,1,1) -> 74 persistent clusters.
// pair q = cid + 74*j ; pmx = q&15 (M pair), nb = q>>4 (N tile).
// MODE 1: gu slice, SwiGLU epilogue -> h hi/lo (NPAIRS = 16*86 = 1376, K=4096)
// MODE 0: out = h @ Wd^T, fp32 epilogue     (NPAIRS = 16*16 = 256,  K=11008)
template<int MODE>
__global__ void __launch_bounds__(NTHREADS, 1) __cluster_dims__(2, 1, 1)
mlp_gemm(const bf16* __restrict__ A_hi, const bf16* __restrict__ A_lo,
         const bf16* __restrict__ B_hi, const bf16* __restrict__ B_lo,
         const bf16* __restrict__ B1_hi, const bf16* __restrict__ B1_lo,
         int K, int ldout,
         float* __restrict__ Cout,
         bf16* __restrict__ Hhi, bf16* __restrict__ Hlo)
{
    extern __shared__ __align__(1024) char smem[];
    const int tid = threadIdx.x;
    const int cid = blockIdx.x >> 1;
    const uint32_t rank = (uint32_t)(blockIdx.x & 1);
    const int NPAIRS = (MODE == 1) ? (16 * 86) : (16 * 16);
    const int nch = K / KC;
    const int ntiles = (NPAIRS - cid + (NCLUSTERS - 1)) / NCLUSTERS;  // >=1 for all cid<74

#if HAS_TC
    const uint32_t sb = smem_u32(smem);
    const int wid = tid >> 5;

    if (wid == 0) tc_alloc_cg2(sb + 0, 512);
    if (tid == 0) {
        const uint32_t ldc = (rank == 0) ? 129u : 128u;
#pragma unroll
        for (int s = 0; s < NSTAGE; ++s) {
            MBARRIER_INIT(sb + MB_MMA(s), 1);
            MBARRIER_INIT(sb + MB_LD(s), ldc);
        }
#pragma unroll
        for (int b = 0; b < 2; ++b) {
            MBARRIER_INIT(sb + MB_TILE(b), 1);
            MBARRIER_INIT(sb + MB_EPI(b), 256);   // 128 local + 128 remote (used on leader)
        }
    }
    __syncthreads();
    uint32_t tmem;
    asm volatile("ld.shared.b32 %0, [%1];" : "=r"(tmem) : "r"(sb));
    CLUSTER_SYNC();

    if (wid >= 4 && wid < 8) {
        // ================= loader warps (128 threads) =================
        const int t = tid - 128;
        long g = 0;
        for (int j = 0; j < ntiles; ++j) {
            const int q = cid + NCLUSTERS * j;
            const int pmx = q & 15, nb = q >> 4;
            const bf16* a_hi = A_hi + (size_t)(pmx * 2 + rank) * BM * K;
            const bf16* a_lo = A_lo + (size_t)(pmx * 2 + rank) * BM * K;
            const bf16 *bh_hi, *bh_lo;
            tile_b_ptrs<MODE>(nb, rank, K, B_hi, B_lo, B1_hi, B1_lo, &bh_hi, &bh_lo);
            for (int i = 0; i < nch; ++i, ++g) {
                const int s = (int)(g % NSTAGE);
                if (g >= NSTAGE)
                    MBARRIER_WAIT_PARITY(sb + MB_MMA(s), (int)((g / NSTAGE - 1) & 1));
                load_chunk128(sb + SMEM_STAGE0 + (uint32_t)s * STAGE_BYTES, t, i * KC, K,
                              a_hi, a_lo, bh_hi, bh_lo);
                cp_arrive(sb + MB_LD(s));
            }
        }
    } else if (wid == 0) {
        if (rank == 0) {
            // ================= MMA issue warp (leader) =================
            long g = 0;
            for (int j = 0; j < ntiles; ++j) {
                const int b = j & 1;
                if (j >= 2)   // buffer reusable only after epilogue of tile j-2
                    MBARRIER_WAIT_PARITY(sb + MB_EPI(b), ((j - 2) >> 1) & 1);
                const uint32_t dbuf = tmem + (uint32_t)b * 256;
                for (int i = 0; i < nch; ++i, ++g) {
                    const int s = (int)(g % NSTAGE);
                    MBARRIER_WAIT_PARITY(sb + MB_LD(s), (int)((g / NSTAGE) & 1));
                    if (elect_one()) {
                        fence_async_cta();
                        if (i == 0) tc_fence_after();   // order vs epilogue TMEM reads
                        const uint32_t stage = sb + SMEM_STAGE0 + (uint32_t)s * STAGE_BYTES;
                        const uint64_t adh = make_desc(stage + OFF_AHI);
                        const uint64_t adl = make_desc(stage + OFF_ALO);
                        const uint64_t bdh = make_desc(stage + OFF_BHI);
                        const uint64_t bdl = make_desc(stage + OFF_BLO);
                        uint32_t en = (i != 0) ? 1u : 0u;
#pragma unroll
                        for (int kk = 0; kk < 4; ++kk) { mma_ss_cg2(dbuf, adh + kk*2, bdh + kk*2, MMA_IDESC, en); en = 1; }
#pragma unroll
                        for (int kk = 0; kk < 4; ++kk) mma_ss_cg2(dbuf, adh + kk*2, bdl + kk*2, MMA_IDESC, 1);
#pragma unroll
                        for (int kk = 0; kk < 4; ++kk) mma_ss_cg2(dbuf, adl + kk*2, bdh + kk*2, MMA_IDESC, 1);
                        tc_commit_mc_cg2(sb + MB_MMA(s), 0x3);
                        if (i == nch - 1) tc_commit_mc_cg2(sb + MB_TILE(b), 0x3);
                    }
                }
            }
        } else {
            // ================= follower relay =================
            const long total = (long)ntiles * nch;
            for (long g = 0; g < total; ++g) {
                const int s = (int)(g % NSTAGE);
                MBARRIER_WAIT_PARITY(sb + MB_LD(s), (int)((g / NSTAGE) & 1));
                if (elect_one()) {
                    fence_async_cta();
                    MBARRIER_ARRIVE_CLUSTER(sb + MB_LD(s), 0);
                }
            }
        }
    } else if (wid >= 8) {
        // ================= epilogue warpgroup (128 threads, warps 8-11) =================
        const int et = tid - 256;                 // 0..127 -> D row within CTA
        for (int j = 0; j < ntiles; ++j) {
            const int b = j & 1;
            MBARRIER_WAIT_PARITY(sb + MB_TILE(b), (j >> 1) & 1);
            tc_fence_after();
            const int q = cid + NCLUSTERS * j;
            const int pmx = q & 15, nb = q >> 4;
            const uint32_t tb = tmem + (uint32_t)b * 256;
            const int m = (pmx * 2 + (int)rank) * BM + et;
            if (MODE == 1) {
                bf16* hh = Hhi + (size_t)m * ldout + (size_t)nb * 128;
                bf16* hl = Hlo + (size_t)m * ldout + (size_t)nb * 128;
#pragma unroll
                for (int c0 = 0; c0 < 128; c0 += 32) {
                    uint32_t gr[32], ur[32];
                    tc_ld32(gr, tb + c0);
                    tc_ld32(ur, tb + 128 + c0);
                    tc_wait_ld();
                    uint32_t hp[16], lp[16];
#pragma unroll
                    for (int jj = 0; jj < 16; ++jj) {
                        float g0 = __uint_as_float(gr[2*jj]);
                        float g1 = __uint_as_float(gr[2*jj+1]);
                        float u0 = __uint_as_float(ur[2*jj]);
                        float u1 = __uint_as_float(ur[2*jj+1]);
                        float h0 = g0 * u0 / (1.0f + __expf(-g0));
                        float h1 = g1 * u1 / (1.0f + __expf(-g1));
                        bf16 a0 = __float2bfloat16(h0);
                        bf16 a1 = __float2bfloat16(h1);
                        __nv_bfloat162 hv = __halves2bfloat162(a0, a1);
                        __nv_bfloat162 lv = __halves2bfloat162(
                            __float2bfloat16(h0 - __bfloat162float(a0)),
                            __float2bfloat16(h1 - __bfloat162float(a1)));
                        hp[jj] = *reinterpret_cast<uint32_t*>(&hv);
                        lp[jj] = *reinterpret_cast<uint32_t*>(&lv);
                    }
#pragma unroll
                    for (int v = 0; v < 4; ++v) {
                        uint4 vh = make_uint4(hp[4*v], hp[4*v+1], hp[4*v+2], hp[4*v+3]);
                        uint4 vl = make_uint4(lp[4*v], lp[4*v+1], lp[4*v+2], lp[4*v+3]);
                        *reinterpret_cast<uint4*>(hh + c0 + v * 8) = vh;
                        *reinterpret_cast<uint4*>(hl + c0 + v * 8) = vl;
                    }
                }
            } else {
                float* co = Cout + (size_t)m * ldout + (size_t)nb * 256;
#pragma unroll
                for (int c0 = 0; c0 < 256; c0 += 32) {
                    uint32_t dr[32];
                    tc_ld32(dr, tb + c0);
                    tc_wait_ld();
#pragma unroll
                    for (int v = 0; v < 8; ++v) {
                        float4 f = make_float4(__uint_as_float(dr[4*v]),
                                               __uint_as_float(dr[4*v+1]),
                                               __uint_as_float(dr[4*v+2]),
                                               __uint_as_float(dr[4*v+3]));
                        *reinterpret_cast<float4*>(co + c0 + v * 4) = f;
                    }
                }
            }
            tc_fence_before();
            // signal buffer free to the LEADER (both CTAs' epilogues must finish)
            if (rank == 0) { MBARRIER_ARRIVE_LOCAL(sb + MB_EPI(b)); }
            else           { MBARRIER_ARRIVE_CLUSTER(sb + MB_EPI(b), 0); }
        }
    }
    // warps 1-3 fall through
    __syncthreads();
    CLUSTER_SYNC();
    if (wid == 0) {
        tc_relinquish_cg2();
        tc_dealloc_cg2(tmem, 512);
    }
    CLUSTER_SYNC();

#else
    // ---------------- SIMT fallback (plain sm_103 target; never the picked cubin) ----
    float* fA  = reinterpret_cast<float*>(smem);          // [8][128]
    float* fB0 = fA  + 8 * 128;
    float* fB1 = fB0 + 8 * 128;
    const int tx = tid & 15;
    const int ty = (tid >> 4) & 15;
    const int lr = (tid & 255) >> 1;
    const int lc = (tid & 1) << 2;

    for (int j = 0; j < ntiles; ++j) {
        const int q = cid + NCLUSTERS * j;
        const int pmx = q & 15, nb = q >> 4;
        const int mbx = pmx * 2 + (int)rank;
        const bf16* a_hi = A_hi + (size_t)mbx * BM * K;
        const bf16* a_lo = A_lo + (size_t)mbx * BM * K;
        const size_t boff = (MODE == 1) ? (size_t)nb * 128 * K : (size_t)nb * 256 * K;
        const bf16* b0_hi = ((MODE == 1 && rank) ? B1_hi : B_hi) + boff;
        const bf16* b0_lo = ((MODE == 1 && rank) ? B1_lo : B_lo) + boff;
        const bf16* b1_hi = (MODE == 1) ? b0_hi : (B_hi + boff + (size_t)128 * K);
        const bf16* b1_lo = (MODE == 1) ? b0_lo : (B_lo + boff + (size_t)128 * K);

        float acc0[8][8], acc1[8][8];
#pragma unroll
        for (int i = 0; i < 8; i++)
#pragma unroll
            for (int jj = 0; jj < 8; jj++) { acc0[i][jj] = 0.0f; acc1[i][jj] = 0.0f; }

        for (int k0 = 0; k0 < K; k0 += 8) {
            __syncthreads();
            if (tid < 256) {
#pragma unroll
                for (int c = 0; c < 4; ++c) {
                    int k = k0 + lc + c;
                    size_t off = (size_t)lr * K + k;
                    fA [(lc + c) * 128 + lr] = __bfloat162float(a_hi[off]) + __bfloat162float(a_lo[off]);
                    fB0[(lc + c) * 128 + lr] = __bfloat162float(b0_hi[off]) + __bfloat162float(b0_lo[off]);
                    fB1[(lc + c) * 128 + lr] = __bfloat162float(b1_hi[off]) + __bfloat162float(b1_lo[off]);
                }
            }
            __syncthreads();
            if (tid < 256) {
#pragma unroll
                for (int k = 0; k < 8; k++) {
                    float ra[8], rb0[8], rb1[8];
#pragma unroll
                    for (int i = 0; i < 8; i++) ra[i]  = fA [k * 128 + ty * 8 + i];
#pragma unroll
                    for (int jj = 0; jj < 8; jj++) { rb0[jj] = fB0[k * 128 + tx * 8 + jj]; rb1[jj] = fB1[k * 128 + tx * 8 + jj]; }
#pragma unroll
                    for (int i = 0; i < 8; i++)
#pragma unroll
                        for (int jj = 0; jj < 8; jj++) {
                            acc0[i][jj] = fmaf(ra[i], rb0[jj], acc0[i][jj]);
                            acc1[i][jj] = fmaf(ra[i], rb1[jj], acc1[i][jj]);
                        }
                }
            }
        }
        if (tid < 256) {
            if (MODE == 1) {
#pragma unroll
                for (int i = 0; i < 8; i++) {
                    int m = mbx * BM + ty * 8 + i;
                    bf16* hh = Hhi + (size_t)m * ldout + (size_t)nb * 128 + tx * 8;
                    bf16* hl = Hlo + (size_t)m * ldout + (size_t)nb * 128 + tx * 8;
#pragma unroll
                    for (int jj = 0; jj < 8; jj++) {
                        float g = acc0[i][jj], u = acc1[i][jj];
                        float h = g * u / (1.0f + __expf(-g));
                        bf16 hv = __float2bfloat16(h);
                        hh[jj] = hv;
                        hl[jj] = __float2bfloat16(h - __bfloat162float(hv));
                    }
                }
            } else {
#pragma unroll
                for (int i = 0; i < 8; i++) {
                    int m = mbx * BM + ty * 8 + i;
                    float* co = Cout + (size_t)m * ldout + (size_t)nb * 256 + tx * 8;
#pragma unroll
                    for (int jj = 0; jj < 8; jj++) { co[jj] = acc0[i][jj]; co[128 + jj] = acc1[i][jj]; }
                }
            }
        }
        __syncthreads();
    }
#endif
}

// ======================= fp32 -> bf16 hi/lo split =======================
__global__ void split_kernel(const float4* __restrict__ src,
                             __nv_bfloat162* __restrict__ hi,
                             __nv_bfloat162* __restrict__ lo, long n4)
{
    long i = (long)blockIdx.x * blockDim.x + threadIdx.x;
    if (i >= n4) return;
    float4 v = src[i];
    bf16 h0 = __float2bfloat16(v.x);
    bf16 h1 = __float2bfloat16(v.y);
    bf16 h2 = __float2bfloat16(v.z);
    bf16 h3 = __float2bfloat16(v.w);
    bf16 l0 = __float2bfloat16(v.x - __bfloat162float(h0));
    bf16 l1 = __float2bfloat16(v.y - __bfloat162float(h1));
    bf16 l2 = __float2bfloat16(v.z - __bfloat162float(h2));
    bf16 l3 = __float2bfloat16(v.w - __bfloat162float(h3));
    hi[2*i]   = __halves2bfloat162(h0, h1);
    hi[2*i+1] = __halves2bfloat162(h2, h3);
    lo[2*i]   = __halves2bfloat162(l0, l1);
    lo[2*i+1] = __halves2bfloat162(l2, l3);
}

// ======================= launch =======================
extern "C" void kernel_launch(void* const* d_in, const int* in_sizes, int n_in,
                              void* d_out, int out_size)
{
    const float* x   = (const float*)d_in[0];
    const float* wgu = (const float*)d_in[1];
    const float* wd  = (const float*)d_in[2];
    float* out       = (float*)d_out;

    bf16 *x_hi, *x_lo, *wgu_hi, *wgu_lo, *wd_hi, *wd_lo, *h_hi, *h_lo;
    cudaGetSymbolAddress((void**)&x_hi,  g_x_hi);
    cudaGetSymbolAddress((void**)&x_lo,  g_x_lo);
    cudaGetSymbolAddress((void**)&wgu_hi, g_wgu_hi);
    cudaGetSymbolAddress((void**)&wgu_lo, g_wgu_lo);
    cudaGetSymbolAddress((void**)&wd_hi, g_wd_hi);
    cudaGetSymbolAddress((void**)&wd_lo, g_wd_lo);
    cudaGetSymbolAddress((void**)&h_hi,  g_h_hi);
    cudaGetSymbolAddress((void**)&h_lo,  g_h_lo);

    cudaFuncSetAttribute(mlp_gemm<0>, cudaFuncAttributeMaxDynamicSharedMemorySize, SMEM_TOTAL);
    cudaFuncSetAttribute(mlp_gemm<1>, cudaFuncAttributeMaxDynamicSharedMemorySize, SMEM_TOTAL);

    // split inputs into bf16 hi/lo
    {
        long n4 = (long)M_DIM * H_DIM / 4;
        split_kernel<<<(unsigned)((n4 + 255) / 256), 256>>>(
            (const float4*)x, (__nv_bfloat162*)x_hi, (__nv_bfloat162*)x_lo, n4);
    }
    {
        long n4 = (long)2 * I_DIM * H_DIM / 4;
        split_kernel<<<(unsigned)((n4 + 255) / 256), 256>>>(
            (const float4*)wgu, (__nv_bfloat162*)wgu_hi, (__nv_bfloat162*)wgu_lo, n4);
    }
    {
        long n4 = (long)H_DIM * I_DIM / 4;
        split_kernel<<<(unsigned)((n4 + 255) / 256), 256>>>(
            (const float4*)wd, (__nv_bfloat162*)wd_hi, (__nv_bfloat162*)wd_lo, n4);
    }

    // GEMM1 (fused SwiGLU + h split): persistent, 148 CTAs (74 clusters)
    mlp_gemm<1><<<dim3(2 * NCLUSTERS, 1, 1), NTHREADS, SMEM_TOTAL>>>(
        x_hi, x_lo,
        wgu_hi, wgu_lo,
        wgu_hi + (size_t)I_DIM * H_DIM, wgu_lo + (size_t)I_DIM * H_DIM,
        H_DIM, I_DIM,
        nullptr, h_hi, h_lo);

    // GEMM2: out = h @ Wd^T: persistent, 148 CTAs (74 clusters)
    mlp_gemm<0><<<dim3(2 * NCLUSTERS, 1, 1), NTHREADS, SMEM_TOTAL>>>(
        h_hi, h_lo,
        wd_hi, wd_lo,
        nullptr, nullptr,
        I_DIM, H_DIM,
        out, nullptr, nullptr);
}

// round 10
// speedup vs baseline: 2.4882x; 1.4644x over previous
#include <cuda_runtime.h>
#include <cuda_fp16.h>
#include <cstdint>
#include <math.h>

typedef __half fp16;

// ---- arch gate: tcgen05 only exists on arch-specific (sm_103a) targets ----
#if defined(__CUDA_ARCH__) && ( \
      defined(__CUDA_ARCH_FEAT_SM103_ALL) || \
      defined(__CUDA_ARCH_FEAT_SM100_ALL) || \
      (defined(__CUDA_ARCH_SPECIFIC__) && (__CUDA_ARCH_SPECIFIC__ == 1030 || __CUDA_ARCH_SPECIFIC__ == 1000)) )
#define HAS_TC 1
#else
#define HAS_TC 0
#endif

// ---- problem dims ----
#define M_DIM 4096
#define H_DIM 4096
#define I_DIM 11008

// ---- tile config: cg2 pair computes M=256 x N=256, persistent clusters ----
#define BM 128          // per CTA
#define KC 64           // fp16 per K-chunk -> 128B rows (SW128 atom)
#define NTHREADS 384    // w0 MMA/relay, w4-7 loaders, w8-11 epilogue
#define NSTAGE 6
#define NCLUSTERS 74

// ---- smem stage layout (bytes): A [128x64 fp16], B-half [128x64 fp16] ----
#define OFF_A 0
#define OFF_B (16*1024)
#define STAGE_BYTES (32*1024)
#define SMEM_STAGE0 1024
#define SMEM_TOTAL (SMEM_STAGE0 + NSTAGE*STAGE_BYTES)   // 197632 B

// mbarrier offsets
#define MB_MMA(s)  (8   + (s)*8)    // 8..48   : per-chunk commit (gates loaders)
#define MB_LD(s)   (56  + (s)*8)    // 56..96  : loads done (129 leader / 128 follower)
#define MB_TILE(b) (104 + (b)*8)    // 104,112 : tile's MMAs complete (gates epilogue)
#define MB_EPI(b)  (120 + (b)*8)    // 120,128 : epilogue done (256 arrives, leader)

// idesc: kind::f16, F32 acc(1<<4), FP16xFP16 (atype=btype=0), N=256, M=256 (pair)
#define MMA_IDESC ((1u<<4)|((256/8)<<17)|((256/16)<<24))

// SW128 K-major smem descriptor base (layout=2, version=1, SBO=64, LBO=1)
#define SMEM_DESC_BASE_SW128 \
    ((uint64_t(2) << 61) | (uint64_t(1) << 46) | (uint64_t(64) << 32) | (uint64_t(1) << 16))

// ---- device scratch (allocation-free rule) ----
__device__ fp16 g_x  [(size_t)M_DIM * H_DIM];
__device__ fp16 g_wgu[(size_t)2 * I_DIM * H_DIM];
__device__ fp16 g_wd [(size_t)H_DIM * I_DIM];
__device__ fp16 g_h  [(size_t)M_DIM * I_DIM];

// ======================= generic PTX helpers =======================

__device__ __forceinline__ uint32_t smem_u32(const void* p) {
    uint32_t a;
    asm("{ .reg .u64 t; cvta.to.shared.u64 t, %1; cvt.u32.u64 %0, t; }" : "=r"(a) : "l"(p));
    return a;
}
__device__ __forceinline__ uint32_t elect_one() {
    uint32_t pred;
    asm volatile("{\n\t.reg .pred p;\n\telect.sync _|p, 0xFFFFFFFF;\n\tselp.b32 %0, 1, 0, p;\n\t}" : "=r"(pred));
    return pred;
}
__device__ __forceinline__ uint32_t swz(uint32_t off) { return off ^ ((off >> 3) & 0x70); }

__device__ __forceinline__ void cp16(uint32_t dst, const void* src) {
    asm volatile("cp.async.cg.shared.global [%0], [%1], 16;" :: "r"(dst), "l"(src) : "memory");
}
// .noinc REQUIRED (default form pre-increments pending count, self-cancelling)
__device__ __forceinline__ void cp_arrive(uint32_t mbar) {
    asm volatile("cp.async.mbarrier.arrive.noinc.shared::cta.b64 [%0];" :: "r"(mbar) : "memory");
}
// LOCAL async-proxy fence (unscoped variant re-serializes in-flight prefetches)
__device__ __forceinline__ void fence_async_cta() {
    asm volatile("fence.proxy.async.shared::cta;" ::: "memory");
}
__device__ __forceinline__ uint64_t make_desc(uint32_t addr) {
    return SMEM_DESC_BASE_SW128 | ((uint64_t)(addr >> 4) & 0x3FFF);
}

#define MBARRIER_INIT(mbar, count) \
    asm volatile("mbarrier.init.shared.b64 [%0], %1;" \
        :: "r"((uint32_t)(mbar)), "r"((uint32_t)(count)) : "memory")

#define MBARRIER_ARRIVE_LOCAL(mbar) \
    asm volatile("mbarrier.arrive.release.cta.shared::cta.b64 _, [%0];" \
        :: "r"((uint32_t)(mbar)) : "memory")

#define MBARRIER_ARRIVE_CLUSTER(local_mbar_addr, target_rank) \
    asm volatile( \
        "{\n\t.reg .b32 remAddr32;\n\t" \
        "mapa.shared::cluster.u32 remAddr32, %0, %1;\n\t" \
        "mbarrier.arrive.release.cluster.shared::cluster.b64 _, [remAddr32];\n\t}" \
        :: "r"((uint32_t)(local_mbar_addr)), "r"((uint32_t)(target_rank)) : "memory")

#define MBARRIER_WAIT_PARITY(mbar_addr, phase_parity) do { \
    uint32_t _mbar = (uint32_t)(mbar_addr); \
    uint32_t _parity = (uint32_t)(phase_parity); \
    uint32_t _done; \
    asm volatile( \
        "{\n\t.reg .pred p;\n\t" \
        "mbarrier.try_wait.parity.acquire.cta.shared::cta.b64 p, [%1], %2;\n\t" \
        "selp.b32 %0, 1, 0, p;\n\t}" \
        : "=r"(_done) : "r"(_mbar), "r"(_parity) : "memory"); \
    if (!_done) { \
        asm volatile( \
            "{\n\t.reg .pred P1;\n\t" \
            "WAIT_LOOP_%=:\n\t" \
            "mbarrier.try_wait.parity.acquire.cta.shared::cta.b64 P1, [%0], %1, 0x989680;\n\t" \
            "@P1 bra.uni WAIT_DONE_%=;\n\t" \
            "bra.uni WAIT_LOOP_%=;\n\t" \
            "WAIT_DONE_%=:\n\t}" \
            :: "r"(_mbar), "r"(_parity) : "memory"); \
    } \
} while (0)

#define CLUSTER_SYNC() do { \
    asm volatile("barrier.cluster.arrive.aligned;" ::: "memory"); \
    asm volatile("barrier.cluster.wait.aligned;" ::: "memory"); \
} while (0)

// ======================= tcgen05 cg2 helpers =======================

__device__ __forceinline__ void mma_ss_cg2(uint32_t d, uint64_t ad, uint64_t bd,
                                           uint32_t idesc, uint32_t en) {
    asm volatile(
        "{\n\t"
        ".reg .pred p;\n\t"
        "setp.ne.u32 p, %4, 0;\n\t"
        "tcgen05.mma.cta_group::2.kind::f16 [%0], %1, %2, %3, {%5, %5, %5, %5, %5, %5, %5, %5}, p;\n\t"
        "}"
        :: "r"(d), "l"(ad), "l"(bd), "r"(idesc), "r"(en), "r"(0u)
        : "memory");
}
__device__ __forceinline__ void tc_alloc_cg2(uint32_t smem_result_addr, uint32_t nCols) {
    asm volatile("tcgen05.alloc.cta_group::2.sync.aligned.shared::cta.b32 [%0], %1;"
        :: "r"(smem_result_addr), "r"(nCols) : "memory");
}
__device__ __forceinline__ void tc_dealloc_cg2(uint32_t tmem_addr, uint32_t nCols) {
    asm volatile("tcgen05.dealloc.cta_group::2.sync.aligned.b32 %0, %1;"
        :: "r"(tmem_addr), "r"(nCols));
}
__device__ __forceinline__ void tc_relinquish_cg2() {
    asm volatile("tcgen05.relinquish_alloc_permit.cta_group::2.sync.aligned;");
}
__device__ __forceinline__ void tc_commit_mc_cg2(uint32_t mbar, uint16_t mask) {
    asm volatile("tcgen05.commit.cta_group::2.mbarrier::arrive::one.shared::cluster.multicast::cluster.b64 [%0], %1;"
        :: "r"(mbar), "h"(mask) : "memory");
}
__device__ __forceinline__ void tc_fence_after() {
    asm volatile("tcgen05.fence::after_thread_sync;" ::: "memory");
}
__device__ __forceinline__ void tc_fence_before() {
    asm volatile("tcgen05.fence::before_thread_sync;" ::: "memory");
}
__device__ __forceinline__ void tc_wait_ld() {
    asm volatile("tcgen05.wait::ld.sync.aligned;" ::: "memory");
}
__device__ __forceinline__ void tc_ld32(uint32_t* r, uint32_t tmem_addr) {
    asm volatile(
        "tcgen05.ld.sync.aligned.32x32b.x32.b32 "
        "{%0, %1, %2, %3, %4, %5, %6, %7, "
        " %8, %9, %10, %11, %12, %13, %14, %15, "
        " %16, %17, %18, %19, %20, %21, %22, %23, "
        " %24, %25, %26, %27, %28, %29, %30, %31}, [%32];"
        : "=r"(r[0]),  "=r"(r[1]),  "=r"(r[2]),  "=r"(r[3]),
          "=r"(r[4]),  "=r"(r[5]),  "=r"(r[6]),  "=r"(r[7]),
          "=r"(r[8]),  "=r"(r[9]),  "=r"(r[10]), "=r"(r[11]),
          "=r"(r[12]), "=r"(r[13]), "=r"(r[14]), "=r"(r[15]),
          "=r"(r[16]), "=r"(r[17]), "=r"(r[18]), "=r"(r[19]),
          "=r"(r[20]), "=r"(r[21]), "=r"(r[22]), "=r"(r[23]),
          "=r"(r[24]), "=r"(r[25]), "=r"(r[26]), "=r"(r[27]),
          "=r"(r[28]), "=r"(r[29]), "=r"(r[30]), "=r"(r[31])
        : "r"(tmem_addr));
}

// ======================= tile loader (128 loader threads) =======================
// Per CTA per chunk: A [128x64 fp16] + B-half [128x64 fp16] = 2048 x 16B units
// /128 threads = 16 cp16 each.
__device__ __forceinline__ void load_chunk128(
    uint32_t sbase, int t, int k0, int K,
    const fp16* a, const fp16* bh)
{
#pragma unroll
    for (int j = 0; j < 8; ++j) {
        int cc = t + j * 128, row = cc >> 3, col = cc & 7;
        cp16(sbase + OFF_A + swz((uint32_t)row * 128 + col * 16),
             a + (size_t)row * K + k0 + col * 8);
    }
#pragma unroll
    for (int j = 0; j < 8; ++j) {
        int cc = t + j * 128, row = cc >> 3, col = cc & 7;
        cp16(sbase + OFF_B + swz((uint32_t)row * 128 + col * 16),
             bh + (size_t)row * K + k0 + col * 8);
    }
}

// ======================= persistent fused GEMM (cg2, fp16 single-product) =========
// grid (148,1,1), cluster (2,1,1) -> 74 persistent clusters.
// pair q = cid + 74*j ; pmx = q&15 (M pair), nb = q>>4 (N tile).
// MODE 1: gu slice, SwiGLU epilogue -> h fp16 (NPAIRS = 16*86 = 1376, K=4096)
// MODE 0: out = h @ Wd^T, fp32 epilogue    (NPAIRS = 16*16 = 256,  K=11008)
template<int MODE>
__global__ void __launch_bounds__(NTHREADS, 1) __cluster_dims__(2, 1, 1)
mlp_gemm(const fp16* __restrict__ A,
         const fp16* __restrict__ B,
         const fp16* __restrict__ B1,
         int K, int ldout,
         float* __restrict__ Cout,
         fp16* __restrict__ H)
{
    extern __shared__ __align__(1024) char smem[];
    const int tid = threadIdx.x;
    const int cid = blockIdx.x >> 1;
    const uint32_t rank = (uint32_t)(blockIdx.x & 1);
    const int NPAIRS = (MODE == 1) ? (16 * 86) : (16 * 16);
    const int nch = K / KC;
    const int ntiles = (NPAIRS - cid + (NCLUSTERS - 1)) / NCLUSTERS;

#if HAS_TC
    const uint32_t sb = smem_u32(smem);
    const int wid = tid >> 5;

    if (wid == 0) tc_alloc_cg2(sb + 0, 512);
    if (tid == 0) {
        const uint32_t ldc = (rank == 0) ? 129u : 128u;
#pragma unroll
        for (int s = 0; s < NSTAGE; ++s) {
            MBARRIER_INIT(sb + MB_MMA(s), 1);
            MBARRIER_INIT(sb + MB_LD(s), ldc);
        }
#pragma unroll
        for (int b = 0; b < 2; ++b) {
            MBARRIER_INIT(sb + MB_TILE(b), 1);
            MBARRIER_INIT(sb + MB_EPI(b), 256);   // 128 local + 128 remote (leader)
        }
    }
    __syncthreads();
    uint32_t tmem;
    asm volatile("ld.shared.b32 %0, [%1];" : "=r"(tmem) : "r"(sb));
    CLUSTER_SYNC();

    if (wid >= 4 && wid < 8) {
        // ================= loader warps (128 threads) =================
        const int t = tid - 128;
        long g = 0;
        for (int j = 0; j < ntiles; ++j) {
            const int q = cid + NCLUSTERS * j;
            const int pmx = q & 15, nb = q >> 4;
            const fp16* a = A + (size_t)(pmx * 2 + rank) * BM * K;
            const fp16* bh = (MODE == 1)
                ? ((rank ? B1 : B) + (size_t)nb * 128 * K)
                : (B + ((size_t)nb * 256 + rank * 128) * K);
            for (int i = 0; i < nch; ++i, ++g) {
                const int s = (int)(g % NSTAGE);
                if (g >= NSTAGE)
                    MBARRIER_WAIT_PARITY(sb + MB_MMA(s), (int)((g / NSTAGE - 1) & 1));
                load_chunk128(sb + SMEM_STAGE0 + (uint32_t)s * STAGE_BYTES, t, i * KC, K, a, bh);
                cp_arrive(sb + MB_LD(s));
            }
        }
    } else if (wid == 0) {
        if (rank == 0) {
            // ================= MMA issue warp (leader) =================
            long g = 0;
            for (int j = 0; j < ntiles; ++j) {
                const int b = j & 1;
                if (j >= 2)
                    MBARRIER_WAIT_PARITY(sb + MB_EPI(b), ((j - 2) >> 1) & 1);
                const uint32_t dbuf = tmem + (uint32_t)b * 256;
                for (int i = 0; i < nch; ++i, ++g) {
                    const int s = (int)(g % NSTAGE);
                    MBARRIER_WAIT_PARITY(sb + MB_LD(s), (int)((g / NSTAGE) & 1));
                    if (elect_one()) {
                        fence_async_cta();
                        if (i == 0) tc_fence_after();   // order vs epilogue TMEM reads
                        const uint32_t stage = sb + SMEM_STAGE0 + (uint32_t)s * STAGE_BYTES;
                        const uint64_t ad = make_desc(stage + OFF_A);
                        const uint64_t bd = make_desc(stage + OFF_B);
                        uint32_t en = (i != 0) ? 1u : 0u;
#pragma unroll
                        for (int kk = 0; kk < 4; ++kk) {
                            mma_ss_cg2(dbuf, ad + kk*2, bd + kk*2, MMA_IDESC, en);
                            en = 1;
                        }
                        tc_commit_mc_cg2(sb + MB_MMA(s), 0x3);
                        if (i == nch - 1) tc_commit_mc_cg2(sb + MB_TILE(b), 0x3);
                    }
                }
            }
        } else {
            // ================= follower relay =================
            const long total = (long)ntiles * nch;
            for (long g = 0; g < total; ++g) {
                const int s = (int)(g % NSTAGE);
                MBARRIER_WAIT_PARITY(sb + MB_LD(s), (int)((g / NSTAGE) & 1));
                if (elect_one()) {
                    fence_async_cta();
                    MBARRIER_ARRIVE_CLUSTER(sb + MB_LD(s), 0);
                }
            }
        }
    } else if (wid >= 8) {
        // ================= epilogue warpgroup (warps 8-11) =================
        const int et = tid - 256;                 // 0..127 -> D row within CTA
        for (int j = 0; j < ntiles; ++j) {
            const int b = j & 1;
            MBARRIER_WAIT_PARITY(sb + MB_TILE(b), (j >> 1) & 1);
            tc_fence_after();
            const int q = cid + NCLUSTERS * j;
            const int pmx = q & 15, nb = q >> 4;
            const uint32_t tb = tmem + (uint32_t)b * 256;
            const int m = (pmx * 2 + (int)rank) * BM + et;
            if (MODE == 1) {
                fp16* hh = H + (size_t)m * ldout + (size_t)nb * 128;
#pragma unroll
                for (int c0 = 0; c0 < 128; c0 += 32) {
                    uint32_t gr[32], ur[32];
                    tc_ld32(gr, tb + c0);
                    tc_ld32(ur, tb + 128 + c0);
                    tc_wait_ld();
                    uint32_t hp[16];
#pragma unroll
                    for (int jj = 0; jj < 16; ++jj) {
                        float g0 = __uint_as_float(gr[2*jj]);
                        float g1 = __uint_as_float(gr[2*jj+1]);
                        float u0 = __uint_as_float(ur[2*jj]);
                        float u1 = __uint_as_float(ur[2*jj+1]);
                        float h0 = g0 * u0 / (1.0f + __expf(-g0));
                        float h1 = g1 * u1 / (1.0f + __expf(-g1));
                        __half2 hv = __floats2half2_rn(h0, h1);
                        hp[jj] = *reinterpret_cast<uint32_t*>(&hv);
                    }
#pragma unroll
                    for (int v = 0; v < 4; ++v) {
                        uint4 vh = make_uint4(hp[4*v], hp[4*v+1], hp[4*v+2], hp[4*v+3]);
                        *reinterpret_cast<uint4*>(hh + c0 + v * 8) = vh;
                    }
                }
            } else {
                float* co = Cout + (size_t)m * ldout + (size_t)nb * 256;
#pragma unroll
                for (int c0 = 0; c0 < 256; c0 += 32) {
                    uint32_t dr[32];
                    tc_ld32(dr, tb + c0);
                    tc_wait_ld();
#pragma unroll
                    for (int v = 0; v < 8; ++v) {
                        float4 f = make_float4(__uint_as_float(dr[4*v]),
                                               __uint_as_float(dr[4*v+1]),
                                               __uint_as_float(dr[4*v+2]),
                                               __uint_as_float(dr[4*v+3]));
                        *reinterpret_cast<float4*>(co + c0 + v * 4) = f;
                    }
                }
            }
            tc_fence_before();
            if (rank == 0) { MBARRIER_ARRIVE_LOCAL(sb + MB_EPI(b)); }
            else           { MBARRIER_ARRIVE_CLUSTER(sb + MB_EPI(b), 0); }
        }
    }
    __syncthreads();
    CLUSTER_SYNC();
    if (wid == 0) {
        tc_relinquish_cg2();
        tc_dealloc_cg2(tmem, 512);
    }
    CLUSTER_SYNC();

#else
    // ---------------- SIMT fallback (plain sm_103 target; never the picked cubin) ----
    float* fA  = reinterpret_cast<float*>(smem);          // [8][128]
    float* fB0 = fA  + 8 * 128;
    float* fB1 = fB0 + 8 * 128;
    const int tx = tid & 15;
    const int ty = (tid >> 4) & 15;
    const int lr = (tid & 255) >> 1;
    const int lc = (tid & 1) << 2;

    for (int j = 0; j < ntiles; ++j) {
        const int q = cid + NCLUSTERS * j;
        const int pmx = q & 15, nb = q >> 4;
        const int mbx = pmx * 2 + (int)rank;
        const fp16* a = A + (size_t)mbx * BM * K;
        const fp16* b0 = (MODE == 1)
            ? ((rank ? B1 : B) + (size_t)nb * 128 * K)
            : (B + (size_t)nb * 256 * K);
        const fp16* b1 = (MODE == 1) ? b0 : (B + ((size_t)nb * 256 + 128) * K);

        float acc0[8][8], acc1[8][8];
#pragma unroll
        for (int i = 0; i < 8; i++)
#pragma unroll
            for (int jj = 0; jj < 8; jj++) { acc0[i][jj] = 0.0f; acc1[i][jj] = 0.0f; }

        for (int k0 = 0; k0 < K; k0 += 8) {
            __syncthreads();
            if (tid < 256) {
#pragma unroll
                for (int c = 0; c < 4; ++c) {
                    int k = k0 + lc + c;
                    size_t off = (size_t)lr * K + k;
                    fA [(lc + c) * 128 + lr] = __half2float(a[off]);
                    fB0[(lc + c) * 128 + lr] = __half2float(b0[off]);
                    fB1[(lc + c) * 128 + lr] = __half2float(b1[off]);
                }
            }
            __syncthreads();
            if (tid < 256) {
#pragma unroll
                for (int k = 0; k < 8; k++) {
                    float ra[8], rb0[8], rb1[8];
#pragma unroll
                    for (int i = 0; i < 8; i++) ra[i]  = fA [k * 128 + ty * 8 + i];
#pragma unroll
                    for (int jj = 0; jj < 8; jj++) { rb0[jj] = fB0[k * 128 + tx * 8 + jj]; rb1[jj] = fB1[k * 128 + tx * 8 + jj]; }
#pragma unroll
                    for (int i = 0; i < 8; i++)
#pragma unroll
                        for (int jj = 0; jj < 8; jj++) {
                            acc0[i][jj] = fmaf(ra[i], rb0[jj], acc0[i][jj]);
                            acc1[i][jj] = fmaf(ra[i], rb1[jj], acc1[i][jj]);
                        }
                }
            }
        }
        if (tid < 256) {
            if (MODE == 1) {
#pragma unroll
                for (int i = 0; i < 8; i++) {
                    int m = mbx * BM + ty * 8 + i;
                    fp16* hh = H + (size_t)m * ldout + (size_t)nb * 128 + tx * 8;
#pragma unroll
                    for (int jj = 0; jj < 8; jj++) {
                        float g = acc0[i][jj], u = acc1[i][jj];
                        float h = g * u / (1.0f + __expf(-g));
                        hh[jj] = __float2half(h);
                    }
                }
            } else {
#pragma unroll
                for (int i = 0; i < 8; i++) {
                    int m = mbx * BM + ty * 8 + i;
                    float* co = Cout + (size_t)m * ldout + (size_t)nb * 256 + tx * 8;
#pragma unroll
                    for (int jj = 0; jj < 8; jj++) { co[jj] = acc0[i][jj]; co[128 + jj] = acc1[i][jj]; }
                }
            }
        }
        __syncthreads();
    }
#endif
}

// ======================= fp32 -> fp16 convert =======================
__global__ void convert_kernel(const float4* __restrict__ src,
                               __half2* __restrict__ dst, long n4)
{
    long i = (long)blockIdx.x * blockDim.x + threadIdx.x;
    if (i >= n4) return;
    float4 v = src[i];
    dst[2*i]   = __floats2half2_rn(v.x, v.y);
    dst[2*i+1] = __floats2half2_rn(v.z, v.w);
}

// ======================= launch =======================
extern "C" void kernel_launch(void* const* d_in, const int* in_sizes, int n_in,
                              void* d_out, int out_size)
{
    const float* x   = (const float*)d_in[0];
    const float* wgu = (const float*)d_in[1];
    const float* wd  = (const float*)d_in[2];
    float* out       = (float*)d_out;

    fp16 *xc, *wguc, *wdc, *hc;
    cudaGetSymbolAddress((void**)&xc,  g_x);
    cudaGetSymbolAddress((void**)&wguc, g_wgu);
    cudaGetSymbolAddress((void**)&wdc, g_wd);
    cudaGetSymbolAddress((void**)&hc,  g_h);

    cudaFuncSetAttribute(mlp_gemm<0>, cudaFuncAttributeMaxDynamicSharedMemorySize, SMEM_TOTAL);
    cudaFuncSetAttribute(mlp_gemm<1>, cudaFuncAttributeMaxDynamicSharedMemorySize, SMEM_TOTAL);

    // convert inputs to fp16
    {
        long n4 = (long)M_DIM * H_DIM / 4;
        convert_kernel<<<(unsigned)((n4 + 255) / 256), 256>>>(
            (const float4*)x, (__half2*)xc, n4);
    }
    {
        long n4 = (long)2 * I_DIM * H_DIM / 4;
        convert_kernel<<<(unsigned)((n4 + 255) / 256), 256>>>(
            (const float4*)wgu, (__half2*)wguc, n4);
    }
    {
        long n4 = (long)H_DIM * I_DIM / 4;
        convert_kernel<<<(unsigned)((n4 + 255) / 256), 256>>>(
            (const float4*)wd, (__half2*)wdc, n4);
    }

    // GEMM1 (fused SwiGLU -> h fp16): persistent, 148 CTAs (74 clusters)
    mlp_gemm<1><<<dim3(2 * NCLUSTERS, 1, 1), NTHREADS, SMEM_TOTAL>>>(
        xc, wguc, wguc + (size_t)I_DIM * H_DIM,
        H_DIM, I_DIM,
        nullptr, hc);

    // GEMM2: out = h @ Wd^T: persistent, 148 CTAs (74 clusters)
    mlp_gemm<0><<<dim3(2 * NCLUSTERS, 1, 1), NTHREADS, SMEM_TOTAL>>>(
        hc, wdc, nullptr,
        I_DIM, H_DIM,
        out, nullptr);
}

// round 11
// speedup vs baseline: 4.3472x; 1.7472x over previous
#include <cuda_runtime.h>
#include <cuda_fp16.h>
#include <cuda.h>
#include <cstdint>
#include <math.h>

typedef __half fp16;

// ---- arch gate: tcgen05 only exists on arch-specific (sm_103a) targets ----
#if defined(__CUDA_ARCH__) && ( \
      defined(__CUDA_ARCH_FEAT_SM103_ALL) || \
      defined(__CUDA_ARCH_FEAT_SM100_ALL) || \
      (defined(__CUDA_ARCH_SPECIFIC__) && (__CUDA_ARCH_SPECIFIC__ == 1030 || __CUDA_ARCH_SPECIFIC__ == 1000)) )
#define HAS_TC 1
#else
#define HAS_TC 0
#endif

// ---- problem dims ----
#define M_DIM 4096
#define H_DIM 4096
#define I_DIM 11008

// ---- tile config: cg2 pair computes M=256 x N=256, persistent clusters ----
#define BM 128          // per CTA
#define KC 64           // fp16 per K-chunk -> 128B rows (SW128 atom)
#define NTHREADS 256    // w0 MMA (leader), w1 TMA producer, w4-7 epilogue
#define NSTAGE 6
#define NCLUSTERS 74

// ---- smem stage layout (bytes): A [128x64 fp16], B-half [128x64 fp16] ----
#define OFF_A 0
#define OFF_B (16*1024)
#define STAGE_BYTES (32*1024)
#define SMEM_STAGE0 1024
#define SMEM_TOTAL (SMEM_STAGE0 + NSTAGE*STAGE_BYTES)   // 197632 B

// bytes delivered per chunk into the PAIR (leader's barrier sees both CTAs)
#define CHUNK_TX_BYTES (4 * 16 * 1024)

// mbarrier offsets
#define MB_MMA(s)  (8   + (s)*8)    // 8..48   : per-chunk commit (gates producers)
#define MB_LD(s)   (56  + (s)*8)    // 56..96  : loads done (leader: 1 arrive + tx)
#define MB_TILE(b) (104 + (b)*8)    // 104,112 : tile's MMAs complete (gates epilogue)
#define MB_EPI(b)  (120 + (b)*8)    // 120,128 : epilogue done (256 arrives, leader)

// idesc: kind::f16, F32 acc(1<<4), FP16xFP16 (atype=btype=0), N=256, M=256 (pair)
#define MMA_IDESC ((1u<<4)|((256/8)<<17)|((256/16)<<24))

// SW128 K-major smem descriptor base (layout=2, version=1, SBO=64, LBO=1)
#define SMEM_DESC_BASE_SW128 \
    ((uint64_t(2) << 61) | (uint64_t(1) << 46) | (uint64_t(64) << 32) | (uint64_t(1) << 16))

// ---- device scratch (allocation-free rule) ----
__device__ fp16 g_x  [(size_t)M_DIM * H_DIM];
__device__ fp16 g_wgu[(size_t)2 * I_DIM * H_DIM];
__device__ fp16 g_wd [(size_t)H_DIM * I_DIM];
__device__ fp16 g_h  [(size_t)M_DIM * I_DIM];

// ======================= generic PTX helpers =======================

__device__ __forceinline__ uint32_t smem_u32(const void* p) {
    uint32_t a;
    asm("{ .reg .u64 t; cvta.to.shared.u64 t, %1; cvt.u32.u64 %0, t; }" : "=r"(a) : "l"(p));
    return a;
}
__device__ __forceinline__ uint32_t elect_one() {
    uint32_t pred;
    asm volatile("{\n\t.reg .pred p;\n\telect.sync _|p, 0xFFFFFFFF;\n\tselp.b32 %0, 1, 0, p;\n\t}" : "=r"(pred));
    return pred;
}

#define MBARRIER_INIT(mbar, count) \
    asm volatile("mbarrier.init.shared.b64 [%0], %1;" \
        :: "r"((uint32_t)(mbar)), "r"((uint32_t)(count)) : "memory")

#define MBARRIER_ARRIVE_LOCAL(mbar) \
    asm volatile("mbarrier.arrive.release.cta.shared::cta.b64 _, [%0];" \
        :: "r"((uint32_t)(mbar)) : "memory")

#define MBARRIER_ARRIVE_CLUSTER(local_mbar_addr, target_rank) \
    asm volatile( \
        "{\n\t.reg .b32 remAddr32;\n\t" \
        "mapa.shared::cluster.u32 remAddr32, %0, %1;\n\t" \
        "mbarrier.arrive.release.cluster.shared::cluster.b64 _, [remAddr32];\n\t}" \
        :: "r"((uint32_t)(local_mbar_addr)), "r"((uint32_t)(target_rank)) : "memory")

#define MBARRIER_EXPECT_TX(mbar, tx_bytes) \
    asm volatile("mbarrier.arrive.expect_tx.shared.b64 _, [%0], %1;" \
        :: "r"((uint32_t)(mbar)), "r"((uint32_t)(tx_bytes)) : "memory")

#define MBARRIER_WAIT_PARITY(mbar_addr, phase_parity) do { \
    uint32_t _mbar = (uint32_t)(mbar_addr); \
    uint32_t _parity = (uint32_t)(phase_parity); \
    uint32_t _done; \
    asm volatile( \
        "{\n\t.reg .pred p;\n\t" \
        "mbarrier.try_wait.parity.acquire.cta.shared::cta.b64 p, [%1], %2;\n\t" \
        "selp.b32 %0, 1, 0, p;\n\t}" \
        : "=r"(_done) : "r"(_mbar), "r"(_parity) : "memory"); \
    if (!_done) { \
        asm volatile( \
            "{\n\t.reg .pred P1;\n\t" \
            "WAIT_LOOP_%=:\n\t" \
            "mbarrier.try_wait.parity.acquire.cta.shared::cta.b64 P1, [%0], %1, 0x989680;\n\t" \
            "@P1 bra.uni WAIT_DONE_%=;\n\t" \
            "bra.uni WAIT_LOOP_%=;\n\t" \
            "WAIT_DONE_%=:\n\t}" \
            :: "r"(_mbar), "r"(_parity) : "memory"); \
    } \
} while (0)

#define CLUSTER_SYNC() do { \
    asm volatile("barrier.cluster.arrive.aligned;" ::: "memory"); \
    asm volatile("barrier.cluster.wait.aligned;" ::: "memory"); \
} while (0)

__device__ __forceinline__ uint64_t make_desc(uint32_t addr) {
    return SMEM_DESC_BASE_SW128 | ((uint64_t)(addr >> 4) & 0x3FFF);
}

// cg2 TMA load: both CTAs execute; complete_tx targets CTA0's (leader's) barrier
// via Sm100MmaPeerBitMask (clear bit 24 of the local barrier address).
__device__ __forceinline__ void tma_cg2(uint32_t dst, const void* map,
                                        int x, int y, uint32_t mbar) {
    asm volatile(
        "{\n\t"
        ".reg .b32 lb;\n\t"
        "and.b32 lb, %5, 0xFEFFFFFF;\n\t"
        "cp.async.bulk.tensor.3d.cta_group::2.shared::cluster.global"
        ".tile.mbarrier::complete_tx::bytes "
        "[%0], [%1, {%2, %3, %4}], [lb];\n\t"
        "}"
        :: "r"(dst), "l"(map), "r"(x), "r"(y), "r"(0), "r"(mbar)
        : "memory");
}

// ======================= tcgen05 cg2 helpers =======================

__device__ __forceinline__ void mma_ss_cg2(uint32_t d, uint64_t ad, uint64_t bd,
                                           uint32_t idesc, uint32_t en) {
    asm volatile(
        "{\n\t"
        ".reg .pred p;\n\t"
        "setp.ne.u32 p, %4, 0;\n\t"
        "tcgen05.mma.cta_group::2.kind::f16 [%0], %1, %2, %3, {%5, %5, %5, %5, %5, %5, %5, %5}, p;\n\t"
        "}"
        :: "r"(d), "l"(ad), "l"(bd), "r"(idesc), "r"(en), "r"(0u)
        : "memory");
}
__device__ __forceinline__ void tc_alloc_cg2(uint32_t smem_result_addr, uint32_t nCols) {
    asm volatile("tcgen05.alloc.cta_group::2.sync.aligned.shared::cta.b32 [%0], %1;"
        :: "r"(smem_result_addr), "r"(nCols) : "memory");
}
__device__ __forceinline__ void tc_dealloc_cg2(uint32_t tmem_addr, uint32_t nCols) {
    asm volatile("tcgen05.dealloc.cta_group::2.sync.aligned.b32 %0, %1;"
        :: "r"(tmem_addr), "r"(nCols));
}
__device__ __forceinline__ void tc_relinquish_cg2() {
    asm volatile("tcgen05.relinquish_alloc_permit.cta_group::2.sync.aligned;");
}
__device__ __forceinline__ void tc_commit_mc_cg2(uint32_t mbar, uint16_t mask) {
    asm volatile("tcgen05.commit.cta_group::2.mbarrier::arrive::one.shared::cluster.multicast::cluster.b64 [%0], %1;"
        :: "r"(mbar), "h"(mask) : "memory");
}
__device__ __forceinline__ void tc_fence_after() {
    asm volatile("tcgen05.fence::after_thread_sync;" ::: "memory");
}
__device__ __forceinline__ void tc_fence_before() {
    asm volatile("tcgen05.fence::before_thread_sync;" ::: "memory");
}
__device__ __forceinline__ void tc_wait_ld() {
    asm volatile("tcgen05.wait::ld.sync.aligned;" ::: "memory");
}
__device__ __forceinline__ void tc_ld32(uint32_t* r, uint32_t tmem_addr) {
    asm volatile(
        "tcgen05.ld.sync.aligned.32x32b.x32.b32 "
        "{%0, %1, %2, %3, %4, %5, %6, %7, "
        " %8, %9, %10, %11, %12, %13, %14, %15, "
        " %16, %17, %18, %19, %20, %21, %22, %23, "
        " %24, %25, %26, %27, %28, %29, %30, %31}, [%32];"
        : "=r"(r[0]),  "=r"(r[1]),  "=r"(r[2]),  "=r"(r[3]),
          "=r"(r[4]),  "=r"(r[5]),  "=r"(r[6]),  "=r"(r[7]),
          "=r"(r[8]),  "=r"(r[9]),  "=r"(r[10]), "=r"(r[11]),
          "=r"(r[12]), "=r"(r[13]), "=r"(r[14]), "=r"(r[15]),
          "=r"(r[16]), "=r"(r[17]), "=r"(r[18]), "=r"(r[19]),
          "=r"(r[20]), "=r"(r[21]), "=r"(r[22]), "=r"(r[23]),
          "=r"(r[24]), "=r"(r[25]), "=r"(r[26]), "=r"(r[27]),
          "=r"(r[28]), "=r"(r[29]), "=r"(r[30]), "=r"(r[31])
        : "r"(tmem_addr));
}

// ======================= persistent fused GEMM (cg2 + TMA, fp16) ==================
// grid (148,1,1), cluster (2,1,1) -> 74 persistent clusters.
// pair q = cid + 74*j ; pmx = q&15 (M pair), nb = q>>4 (N tile).
// MODE 1: gu slice, SwiGLU epilogue -> h fp16 (NPAIRS = 1376, K=4096)
//         B rows: rank0 -> nb*128 (gate), rank1 -> I_DIM + nb*128 (up), one map.
// MODE 0: out = h @ Wd^T, fp32 epilogue    (NPAIRS = 256, K=11008)
//         B rows: nb*256 + rank*128.
template<int MODE>
__global__ void __launch_bounds__(NTHREADS, 1) __cluster_dims__(2, 1, 1)
mlp_gemm(const __grid_constant__ CUtensorMap tma_a,
         const __grid_constant__ CUtensorMap tma_b,
         const fp16* __restrict__ A,
         const fp16* __restrict__ B,
         const fp16* __restrict__ B1,
         int K, int ldout,
         float* __restrict__ Cout,
         fp16* __restrict__ H)
{
    extern __shared__ __align__(1024) char smem[];
    const int tid = threadIdx.x;
    const int cid = blockIdx.x >> 1;
    const uint32_t rank = (uint32_t)(blockIdx.x & 1);
    const int NPAIRS = (MODE == 1) ? (16 * 86) : (16 * 16);
    const int nch = K / KC;
    const int ntiles = (NPAIRS - cid + (NCLUSTERS - 1)) / NCLUSTERS;

#if HAS_TC
    const uint32_t sb = smem_u32(smem);
    const int wid = tid >> 5;

    if (wid == 0) tc_alloc_cg2(sb + 0, 512);
    if (tid == 0) {
#pragma unroll
        for (int s = 0; s < NSTAGE; ++s) {
            MBARRIER_INIT(sb + MB_MMA(s), 1);
            MBARRIER_INIT(sb + MB_LD(s), 1);     // 1 arrive (expect_tx) + tx bytes
        }
#pragma unroll
        for (int b = 0; b < 2; ++b) {
            MBARRIER_INIT(sb + MB_TILE(b), 1);
            MBARRIER_INIT(sb + MB_EPI(b), 256);  // 128 local + 128 remote (leader)
        }
    }
    __syncthreads();
    uint32_t tmem;
    asm volatile("ld.shared.b32 %0, [%1];" : "=r"(tmem) : "r"(sb));
    CLUSTER_SYNC();

    if (wid == 1) {
        // ================= TMA producer (single thread per CTA) =================
        if (elect_one()) {
            long g = 0;
            for (int j = 0; j < ntiles; ++j) {
                const int q = cid + NCLUSTERS * j;
                const int pmx = q & 15, nb = q >> 4;
                const int arow = (pmx * 2 + (int)rank) * BM;
                const int brow = (MODE == 1)
                    ? ((int)rank * I_DIM + nb * 128)
                    : (nb * 256 + (int)rank * 128);
                for (int i = 0; i < nch; ++i, ++g) {
                    const int s = (int)(g % NSTAGE);
                    if (g >= NSTAGE)
                        MBARRIER_WAIT_PARITY(sb + MB_MMA(s), (int)((g / NSTAGE - 1) & 1));
                    const uint32_t stage = sb + SMEM_STAGE0 + (uint32_t)s * STAGE_BYTES;
                    if (rank == 0)
                        MBARRIER_EXPECT_TX(sb + MB_LD(s), CHUNK_TX_BYTES);
                    tma_cg2(stage + OFF_A, &tma_a, i * KC, arow, sb + MB_LD(s));
                    tma_cg2(stage + OFF_B, &tma_b, i * KC, brow, sb + MB_LD(s));
                }
            }
        }
    } else if (wid == 0 && rank == 0) {
        // ================= MMA issue warp (leader only) =================
        long g = 0;
        for (int j = 0; j < ntiles; ++j) {
            const int b = j & 1;
            if (j >= 2)
                MBARRIER_WAIT_PARITY(sb + MB_EPI(b), ((j - 2) >> 1) & 1);
            tc_fence_after();                     // order vs epilogue TMEM reads
            const uint32_t dbuf = tmem + (uint32_t)b * 256;
            for (int i = 0; i < nch; ++i, ++g) {
                const int s = (int)(g % NSTAGE);
                MBARRIER_WAIT_PARITY(sb + MB_LD(s), (int)((g / NSTAGE) & 1));
                if (elect_one()) {
                    const uint32_t stage = sb + SMEM_STAGE0 + (uint32_t)s * STAGE_BYTES;
                    const uint64_t ad = make_desc(stage + OFF_A);
                    const uint64_t bd = make_desc(stage + OFF_B);
                    uint32_t en = (i != 0) ? 1u : 0u;
#pragma unroll
                    for (int kk = 0; kk < 4; ++kk) {
                        mma_ss_cg2(dbuf, ad + kk*2, bd + kk*2, MMA_IDESC, en);
                        en = 1;
                    }
                    tc_commit_mc_cg2(sb + MB_MMA(s), 0x3);
                    if (i == nch - 1) tc_commit_mc_cg2(sb + MB_TILE(b), 0x3);
                }
            }
        }
    } else if (wid >= 4) {
        // ================= epilogue warpgroup (warps 4-7, 128 threads) ===========
        const int et = tid - 128;                 // 0..127 -> D row within CTA
        for (int j = 0; j < ntiles; ++j) {
            const int b = j & 1;
            MBARRIER_WAIT_PARITY(sb + MB_TILE(b), (j >> 1) & 1);
            tc_fence_after();
            const int q = cid + NCLUSTERS * j;
            const int pmx = q & 15, nb = q >> 4;
            const uint32_t tb = tmem + (uint32_t)b * 256;
            const int m = (pmx * 2 + (int)rank) * BM + et;
            if (MODE == 1) {
                fp16* hh = H + (size_t)m * ldout + (size_t)nb * 128;
#pragma unroll
                for (int c0 = 0; c0 < 128; c0 += 32) {
                    uint32_t gr[32], ur[32];
                    tc_ld32(gr, tb + c0);
                    tc_ld32(ur, tb + 128 + c0);
                    tc_wait_ld();
                    uint32_t hp[16];
#pragma unroll
                    for (int jj = 0; jj < 16; ++jj) {
                        float g0 = __uint_as_float(gr[2*jj]);
                        float g1 = __uint_as_float(gr[2*jj+1]);
                        float u0 = __uint_as_float(ur[2*jj]);
                        float u1 = __uint_as_float(ur[2*jj+1]);
                        float h0 = g0 * u0 / (1.0f + __expf(-g0));
                        float h1 = g1 * u1 / (1.0f + __expf(-g1));
                        __half2 hv = __floats2half2_rn(h0, h1);
                        hp[jj] = *reinterpret_cast<uint32_t*>(&hv);
                    }
#pragma unroll
                    for (int v = 0; v < 4; ++v) {
                        uint4 vh = make_uint4(hp[4*v], hp[4*v+1], hp[4*v+2], hp[4*v+3]);
                        *reinterpret_cast<uint4*>(hh + c0 + v * 8) = vh;
                    }
                }
            } else {
                float* co = Cout + (size_t)m * ldout + (size_t)nb * 256;
#pragma unroll
                for (int c0 = 0; c0 < 256; c0 += 32) {
                    uint32_t dr[32];
                    tc_ld32(dr, tb + c0);
                    tc_wait_ld();
#pragma unroll
                    for (int v = 0; v < 8; ++v) {
                        float4 f = make_float4(__uint_as_float(dr[4*v]),
                                               __uint_as_float(dr[4*v+1]),
                                               __uint_as_float(dr[4*v+2]),
                                               __uint_as_float(dr[4*v+3]));
                        *reinterpret_cast<float4*>(co + c0 + v * 4) = f;
                    }
                }
            }
            tc_fence_before();
            if (rank == 0) { MBARRIER_ARRIVE_LOCAL(sb + MB_EPI(b)); }
            else           { MBARRIER_ARRIVE_CLUSTER(sb + MB_EPI(b), 0); }
        }
    }
    __syncthreads();
    CLUSTER_SYNC();
    if (wid == 0) {
        tc_relinquish_cg2();
        tc_dealloc_cg2(tmem, 512);
    }
    CLUSTER_SYNC();

#else
    // ---------------- SIMT fallback (plain sm_103 target; never the picked cubin) ----
    float* fA  = reinterpret_cast<float*>(smem);          // [8][128]
    float* fB0 = fA  + 8 * 128;
    float* fB1 = fB0 + 8 * 128;
    const int tx = tid & 15;
    const int ty = (tid >> 4) & 15;
    const int lr = (tid & 255) >> 1;
    const int lc = (tid & 1) << 2;

    for (int j = 0; j < ntiles; ++j) {
        const int q = cid + NCLUSTERS * j;
        const int pmx = q & 15, nb = q >> 4;
        const int mbx = pmx * 2 + (int)rank;
        const fp16* a = A + (size_t)mbx * BM * K;
        const fp16* b0 = (MODE == 1)
            ? ((rank ? B1 : B) + (size_t)nb * 128 * K)
            : (B + (size_t)nb * 256 * K);
        const fp16* b1 = (MODE == 1) ? b0 : (B + ((size_t)nb * 256 + 128) * K);

        float acc0[8][8], acc1[8][8];
#pragma unroll
        for (int i = 0; i < 8; i++)
#pragma unroll
            for (int jj = 0; jj < 8; jj++) { acc0[i][jj] = 0.0f; acc1[i][jj] = 0.0f; }

        for (int k0 = 0; k0 < K; k0 += 8) {
            __syncthreads();
            if (tid < 256) {
#pragma unroll
                for (int c = 0; c < 4; ++c) {
                    int k = k0 + lc + c;
                    size_t off = (size_t)lr * K + k;
                    fA [(lc + c) * 128 + lr] = __half2float(a[off]);
                    fB0[(lc + c) * 128 + lr] = __half2float(b0[off]);
                    fB1[(lc + c) * 128 + lr] = __half2float(b1[off]);
                }
            }
            __syncthreads();
            if (tid < 256) {
#pragma unroll
                for (int k = 0; k < 8; k++) {
                    float ra[8], rb0[8], rb1[8];
#pragma unroll
                    for (int i = 0; i < 8; i++) ra[i]  = fA [k * 128 + ty * 8 + i];
#pragma unroll
                    for (int jj = 0; jj < 8; jj++) { rb0[jj] = fB0[k * 128 + tx * 8 + jj]; rb1[jj] = fB1[k * 128 + tx * 8 + jj]; }
#pragma unroll
                    for (int i = 0; i < 8; i++)
#pragma unroll
                        for (int jj = 0; jj < 8; jj++) {
                            acc0[i][jj] = fmaf(ra[i], rb0[jj], acc0[i][jj]);
                            acc1[i][jj] = fmaf(ra[i], rb1[jj], acc1[i][jj]);
                        }
                }
            }
        }
        if (tid < 256) {
            if (MODE == 1) {
#pragma unroll
                for (int i = 0; i < 8; i++) {
                    int m = mbx * BM + ty * 8 + i;
                    fp16* hh = H + (size_t)m * ldout + (size_t)nb * 128 + tx * 8;
#pragma unroll
                    for (int jj = 0; jj < 8; jj++) {
                        float g = acc0[i][jj], u = acc1[i][jj];
                        float h = g * u / (1.0f + __expf(-g));
                        hh[jj] = __float2half(h);
                    }
                }
            } else {
#pragma unroll
                for (int i = 0; i < 8; i++) {
                    int m = mbx * BM + ty * 8 + i;
                    float* co = Cout + (size_t)m * ldout + (size_t)nb * 256 + tx * 8;
#pragma unroll
                    for (int jj = 0; jj < 8; jj++) { co[jj] = acc0[i][jj]; co[128 + jj] = acc1[i][jj]; }
                }
            }
        }
        __syncthreads();
    }
#endif
}

// ======================= fp32 -> fp16 convert =======================
__global__ void convert_kernel(const float4* __restrict__ src,
                               __half2* __restrict__ dst, long n4)
{
    long i = (long)blockIdx.x * blockDim.x + threadIdx.x;
    if (i >= n4) return;
    float4 v = src[i];
    dst[2*i]   = __floats2half2_rn(v.x, v.y);
    dst[2*i+1] = __floats2half2_rn(v.z, v.w);
}

// ======================= host: tensormap building =======================

typedef CUresult (*EncodeTiledFn)(
    CUtensorMap*, CUtensorMapDataType, cuuint32_t, void*,
    const cuuint64_t*, const cuuint64_t*, const cuuint32_t*, const cuuint32_t*,
    CUtensorMapInterleave, CUtensorMapSwizzle, CUtensorMapL2promotion,
    CUtensorMapFloatOOBfill);

static void build_map(EncodeTiledFn enc, CUtensorMap* m, void* base,
                      unsigned long long dim0, unsigned long long dim1)
{
    cuuint64_t dims[3]    = {dim0, dim1, 1};
    cuuint64_t strides[2] = {dim0 * 2ull, dim0 * dim1 * 2ull};
    cuuint32_t box[3]     = {KC, BM, 1};          // 64 fp16 = 128B (SW128 atom), 128 rows
    cuuint32_t es[3]      = {1, 1, 1};
    enc(m, CU_TENSOR_MAP_DATA_TYPE_FLOAT16, 3, base, dims, strides, box, es,
        CU_TENSOR_MAP_INTERLEAVE_NONE, CU_TENSOR_MAP_SWIZZLE_128B,
        CU_TENSOR_MAP_L2_PROMOTION_L2_128B, CU_TENSOR_MAP_FLOAT_OOB_FILL_NONE);
}

// ======================= launch =======================
extern "C" void kernel_launch(void* const* d_in, const int* in_sizes, int n_in,
                              void* d_out, int out_size)
{
    const float* x   = (const float*)d_in[0];
    const float* wgu = (const float*)d_in[1];
    const float* wd  = (const float*)d_in[2];
    float* out       = (float*)d_out;

    fp16 *xc, *wguc, *wdc, *hc;
    cudaGetSymbolAddress((void**)&xc,  g_x);
    cudaGetSymbolAddress((void**)&wguc, g_wgu);
    cudaGetSymbolAddress((void**)&wdc, g_wd);
    cudaGetSymbolAddress((void**)&hc,  g_h);

    // driver entry point for tensormap encoding (avoids -lcuda link dependency)
    void* fn = nullptr;
    cudaDriverEntryPointQueryResult qr;
    cudaGetDriverEntryPoint("cuTensorMapEncodeTiled", &fn, cudaEnableDefault, &qr);
    EncodeTiledFn enc = (EncodeTiledFn)fn;

    CUtensorMap map_x, map_wgu, map_h, map_wd;
    build_map(enc, &map_x,   xc,   H_DIM, M_DIM);          // [4096, 4096]
    build_map(enc, &map_wgu, wguc, H_DIM, 2ull * I_DIM);   // [4096, 22016]
    build_map(enc, &map_h,   hc,   I_DIM, M_DIM);          // [11008, 4096]
    build_map(enc, &map_wd,  wdc,  I_DIM, H_DIM);          // [11008, 4096]

    cudaFuncSetAttribute(mlp_gemm<0>, cudaFuncAttributeMaxDynamicSharedMemorySize, SMEM_TOTAL);
    cudaFuncSetAttribute(mlp_gemm<1>, cudaFuncAttributeMaxDynamicSharedMemorySize, SMEM_TOTAL);

    // convert inputs to fp16
    {
        long n4 = (long)M_DIM * H_DIM / 4;
        convert_kernel<<<(unsigned)((n4 + 255) / 256), 256>>>(
            (const float4*)x, (__half2*)xc, n4);
    }
    {
        long n4 = (long)2 * I_DIM * H_DIM / 4;
        convert_kernel<<<(unsigned)((n4 + 255) / 256), 256>>>(
            (const float4*)wgu, (__half2*)wguc, n4);
    }
    {
        long n4 = (long)H_DIM * I_DIM / 4;
        convert_kernel<<<(unsigned)((n4 + 255) / 256), 256>>>(
            (const float4*)wd, (__half2*)wdc, n4);
    }

    // GEMM1 (fused SwiGLU -> h fp16): persistent, 148 CTAs (74 clusters)
    mlp_gemm<1><<<dim3(2 * NCLUSTERS, 1, 1), NTHREADS, SMEM_TOTAL>>>(
        map_x, map_wgu,
        xc, wguc, wguc + (size_t)I_DIM * H_DIM,
        H_DIM, I_DIM,
        nullptr, hc);

    // GEMM2: out = h @ Wd^T: persistent, 148 CTAs (74 clusters)
    mlp_gemm<0><<<dim3(2 * NCLUSTERS, 1, 1), NTHREADS, SMEM_TOTAL>>>(
        map_h, map_wd,
        hc, wdc, nullptr,
        I_DIM, H_DIM,
        out, nullptr);
}

// round 12
// speedup vs baseline: 4.5142x; 1.0384x over previous
#include <cuda_runtime.h>
#include <cuda_fp16.h>
#include <cuda.h>
#include <cstdint>
#include <math.h>

typedef __half fp16;

// ---- arch gate: tcgen05 only exists on arch-specific (sm_103a) targets ----
#if defined(__CUDA_ARCH__) && ( \
      defined(__CUDA_ARCH_FEAT_SM103_ALL) || \
      defined(__CUDA_ARCH_FEAT_SM100_ALL) || \
      (defined(__CUDA_ARCH_SPECIFIC__) && (__CUDA_ARCH_SPECIFIC__ == 1030 || __CUDA_ARCH_SPECIFIC__ == 1000)) )
#define HAS_TC 1
#else
#define HAS_TC 0
#endif

// ---- problem dims ----
#define M_DIM 4096
#define H_DIM 4096
#define I_DIM 11008

// ---- tile config: cg2 pair computes M=256 x N=256, persistent clusters ----
#define BM 128          // per CTA
#define KC 64           // fp16 per K-chunk -> 128B rows (SW128 atom)
#define NTHREADS 256    // w0 MMA (leader), w1 TMA producer, w2-3 wd-convert, w4-7 epilogue
#define NSTAGE 6
#define NCLUSTERS 74

// ---- smem stage layout (bytes): A [128x64 fp16], B-half [128x64 fp16] ----
#define OFF_A 0
#define OFF_B (16*1024)
#define STAGE_BYTES (32*1024)
#define SMEM_STAGE0 1024
#define SMEM_TOTAL (SMEM_STAGE0 + NSTAGE*STAGE_BYTES)   // 197632 B

// bytes delivered per chunk into the PAIR (leader's barrier sees both CTAs)
#define CHUNK_TX_BYTES (4 * 16 * 1024)

// mbarrier offsets
#define MB_MMA(s)  (8   + (s)*8)    // 8..48   : per-chunk commit (gates producers)
#define MB_LD(s)   (56  + (s)*8)    // 56..96  : loads done (leader: 1 arrive + tx)
#define MB_TILE(b) (104 + (b)*8)    // 104,112 : tile's MMAs complete (gates epilogue)
#define MB_EPI(b)  (120 + (b)*8)    // 120,128 : epilogue done (256 arrives, leader)

// idesc: kind::f16, F32 acc(1<<4), FP16xFP16 (atype=btype=0), N=256, M=256 (pair)
#define MMA_IDESC ((1u<<4)|((256/8)<<17)|((256/16)<<24))

// SW128 K-major smem descriptor base (layout=2, version=1, SBO=64, LBO=1)
#define SMEM_DESC_BASE_SW128 \
    ((uint64_t(2) << 61) | (uint64_t(1) << 46) | (uint64_t(64) << 32) | (uint64_t(1) << 16))

// ---- device scratch (allocation-free rule) ----
__device__ fp16 g_x  [(size_t)M_DIM * H_DIM];
__device__ fp16 g_wgu[(size_t)2 * I_DIM * H_DIM];
__device__ fp16 g_wd [(size_t)H_DIM * I_DIM];
__device__ fp16 g_h  [(size_t)M_DIM * I_DIM];

// ======================= generic PTX helpers =======================

__device__ __forceinline__ uint32_t smem_u32(const void* p) {
    uint32_t a;
    asm("{ .reg .u64 t; cvta.to.shared.u64 t, %1; cvt.u32.u64 %0, t; }" : "=r"(a) : "l"(p));
    return a;
}
__device__ __forceinline__ uint32_t elect_one() {
    uint32_t pred;
    asm volatile("{\n\t.reg .pred p;\n\telect.sync _|p, 0xFFFFFFFF;\n\tselp.b32 %0, 1, 0, p;\n\t}" : "=r"(pred));
    return pred;
}

#define MBARRIER_INIT(mbar, count) \
    asm volatile("mbarrier.init.shared.b64 [%0], %1;" \
        :: "r"((uint32_t)(mbar)), "r"((uint32_t)(count)) : "memory")

#define MBARRIER_ARRIVE_LOCAL(mbar) \
    asm volatile("mbarrier.arrive.release.cta.shared::cta.b64 _, [%0];" \
        :: "r"((uint32_t)(mbar)) : "memory")

#define MBARRIER_ARRIVE_CLUSTER(local_mbar_addr, target_rank) \
    asm volatile( \
        "{\n\t.reg .b32 remAddr32;\n\t" \
        "mapa.shared::cluster.u32 remAddr32, %0, %1;\n\t" \
        "mbarrier.arrive.release.cluster.shared::cluster.b64 _, [remAddr32];\n\t}" \
        :: "r"((uint32_t)(local_mbar_addr)), "r"((uint32_t)(target_rank)) : "memory")

#define MBARRIER_EXPECT_TX(mbar, tx_bytes) \
    asm volatile("mbarrier.arrive.expect_tx.shared.b64 _, [%0], %1;" \
        :: "r"((uint32_t)(mbar)), "r"((uint32_t)(tx_bytes)) : "memory")

#define MBARRIER_WAIT_PARITY(mbar_addr, phase_parity) do { \
    uint32_t _mbar = (uint32_t)(mbar_addr); \
    uint32_t _parity = (uint32_t)(phase_parity); \
    uint32_t _done; \
    asm volatile( \
        "{\n\t.reg .pred p;\n\t" \
        "mbarrier.try_wait.parity.acquire.cta.shared::cta.b64 p, [%1], %2;\n\t" \
        "selp.b32 %0, 1, 0, p;\n\t}" \
        : "=r"(_done) : "r"(_mbar), "r"(_parity) : "memory"); \
    if (!_done) { \
        asm volatile( \
            "{\n\t.reg .pred P1;\n\t" \
            "WAIT_LOOP_%=:\n\t" \
            "mbarrier.try_wait.parity.acquire.cta.shared::cta.b64 P1, [%0], %1, 0x989680;\n\t" \
            "@P1 bra.uni WAIT_DONE_%=;\n\t" \
            "bra.uni WAIT_LOOP_%=;\n\t" \
            "WAIT_DONE_%=:\n\t}" \
            :: "r"(_mbar), "r"(_parity) : "memory"); \
    } \
} while (0)

#define CLUSTER_SYNC() do { \
    asm volatile("barrier.cluster.arrive.aligned;" ::: "memory"); \
    asm volatile("barrier.cluster.wait.aligned;" ::: "memory"); \
} while (0)

__device__ __forceinline__ uint64_t make_desc(uint32_t addr) {
    return SMEM_DESC_BASE_SW128 | ((uint64_t)(addr >> 4) & 0x3FFF);
}

// cg2 TMA load: both CTAs execute; complete_tx targets CTA0's (leader's) barrier
// via Sm100MmaPeerBitMask (clear bit 24 of the local barrier address).
__device__ __forceinline__ void tma_cg2(uint32_t dst, const void* map,
                                        int x, int y, uint32_t mbar) {
    asm volatile(
        "{\n\t"
        ".reg .b32 lb;\n\t"
        "and.b32 lb, %5, 0xFEFFFFFF;\n\t"
        "cp.async.bulk.tensor.3d.cta_group::2.shared::cluster.global"
        ".tile.mbarrier::complete_tx::bytes "
        "[%0], [%1, {%2, %3, %4}], [lb];\n\t"
        "}"
        :: "r"(dst), "l"(map), "r"(x), "r"(y), "r"(0), "r"(mbar)
        : "memory");
}

// ======================= tcgen05 cg2 helpers =======================

__device__ __forceinline__ void mma_ss_cg2(uint32_t d, uint64_t ad, uint64_t bd,
                                           uint32_t idesc, uint32_t en) {
    asm volatile(
        "{\n\t"
        ".reg .pred p;\n\t"
        "setp.ne.u32 p, %4, 0;\n\t"
        "tcgen05.mma.cta_group::2.kind::f16 [%0], %1, %2, %3, {%5, %5, %5, %5, %5, %5, %5, %5}, p;\n\t"
        "}"
        :: "r"(d), "l"(ad), "l"(bd), "r"(idesc), "r"(en), "r"(0u)
        : "memory");
}
__device__ __forceinline__ void tc_alloc_cg2(uint32_t smem_result_addr, uint32_t nCols) {
    asm volatile("tcgen05.alloc.cta_group::2.sync.aligned.shared::cta.b32 [%0], %1;"
        :: "r"(smem_result_addr), "r"(nCols) : "memory");
}
__device__ __forceinline__ void tc_dealloc_cg2(uint32_t tmem_addr, uint32_t nCols) {
    asm volatile("tcgen05.dealloc.cta_group::2.sync.aligned.b32 %0, %1;"
        :: "r"(tmem_addr), "r"(nCols));
}
__device__ __forceinline__ void tc_relinquish_cg2() {
    asm volatile("tcgen05.relinquish_alloc_permit.cta_group::2.sync.aligned;");
}
__device__ __forceinline__ void tc_commit_mc_cg2(uint32_t mbar, uint16_t mask) {
    asm volatile("tcgen05.commit.cta_group::2.mbarrier::arrive::one.shared::cluster.multicast::cluster.b64 [%0], %1;"
        :: "r"(mbar), "h"(mask) : "memory");
}
__device__ __forceinline__ void tc_fence_after() {
    asm volatile("tcgen05.fence::after_thread_sync;" ::: "memory");
}
__device__ __forceinline__ void tc_fence_before() {
    asm volatile("tcgen05.fence::before_thread_sync;" ::: "memory");
}
__device__ __forceinline__ void tc_wait_ld() {
    asm volatile("tcgen05.wait::ld.sync.aligned;" ::: "memory");
}
__device__ __forceinline__ void tc_ld32(uint32_t* r, uint32_t tmem_addr) {
    asm volatile(
        "tcgen05.ld.sync.aligned.32x32b.x32.b32 "
        "{%0, %1, %2, %3, %4, %5, %6, %7, "
        " %8, %9, %10, %11, %12, %13, %14, %15, "
        " %16, %17, %18, %19, %20, %21, %22, %23, "
        " %24, %25, %26, %27, %28, %29, %30, %31}, [%32];"
        : "=r"(r[0]),  "=r"(r[1]),  "=r"(r[2]),  "=r"(r[3]),
          "=r"(r[4]),  "=r"(r[5]),  "=r"(r[6]),  "=r"(r[7]),
          "=r"(r[8]),  "=r"(r[9]),  "=r"(r[10]), "=r"(r[11]),
          "=r"(r[12]), "=r"(r[13]), "=r"(r[14]), "=r"(r[15]),
          "=r"(r[16]), "=r"(r[17]), "=r"(r[18]), "=r"(r[19]),
          "=r"(r[20]), "=r"(r[21]), "=r"(r[22]), "=r"(r[23]),
          "=r"(r[24]), "=r"(r[25]), "=r"(r[26]), "=r"(r[27]),
          "=r"(r[28]), "=r"(r[29]), "=r"(r[30]), "=r"(r[31])
        : "r"(tmem_addr));
}

// ======================= persistent fused GEMM (cg2 + TMA, fp16) ==================
// grid (148,1,1), cluster (2,1,1) -> 74 persistent clusters.
// pair q = cid + 74*j ; pmx = q&15 (M pair), nb = q>>4 (N tile).
// MODE 1: gu slice, SwiGLU epilogue -> h fp16 (NPAIRS = 1376, K=4096).
//         Warps 2-3 additionally convert wd fp32->fp16 (consumed only by GEMM2,
//         which is stream-ordered after this kernel) using otherwise-idle lanes.
// MODE 0: out = h @ Wd^T, fp32 epilogue    (NPAIRS = 256, K=11008)
template<int MODE>
__global__ void __launch_bounds__(NTHREADS, 1) __cluster_dims__(2, 1, 1)
mlp_gemm(const __grid_constant__ CUtensorMap tma_a,
         const __grid_constant__ CUtensorMap tma_b,
         const fp16* __restrict__ A,
         const fp16* __restrict__ B,
         const fp16* __restrict__ B1,
         int K, int ldout,
         float* __restrict__ Cout,
         fp16* __restrict__ H,
         const float4* __restrict__ wd_src,
         __half2* __restrict__ wd_dst,
         long wd_n4)
{
    extern __shared__ __align__(1024) char smem[];
    const int tid = threadIdx.x;
    const int cid = blockIdx.x >> 1;
    const uint32_t rank = (uint32_t)(blockIdx.x & 1);
    const int NPAIRS = (MODE == 1) ? (16 * 86) : (16 * 16);
    const int nch = K / KC;
    const int ntiles = (NPAIRS - cid + (NCLUSTERS - 1)) / NCLUSTERS;

#if HAS_TC
    const uint32_t sb = smem_u32(smem);
    const int wid = tid >> 5;

    if (wid == 0) tc_alloc_cg2(sb + 0, 512);
    if (tid == 0) {
#pragma unroll
        for (int s = 0; s < NSTAGE; ++s) {
            MBARRIER_INIT(sb + MB_MMA(s), 1);
            MBARRIER_INIT(sb + MB_LD(s), 1);     // 1 arrive (expect_tx) + tx bytes
        }
#pragma unroll
        for (int b = 0; b < 2; ++b) {
            MBARRIER_INIT(sb + MB_TILE(b), 1);
            MBARRIER_INIT(sb + MB_EPI(b), 256);  // 128 local + 128 remote (leader)
        }
    }
    __syncthreads();
    uint32_t tmem;
    asm volatile("ld.shared.b32 %0, [%1];" : "=r"(tmem) : "r"(sb));
    CLUSTER_SYNC();

    if (wid == 1) {
        // ================= TMA producer (single thread per CTA) =================
        if (elect_one()) {
            long g = 0;
            for (int j = 0; j < ntiles; ++j) {
                const int q = cid + NCLUSTERS * j;
                const int pmx = q & 15, nb = q >> 4;
                const int arow = (pmx * 2 + (int)rank) * BM;
                const int brow = (MODE == 1)
                    ? ((int)rank * I_DIM + nb * 128)
                    : (nb * 256 + (int)rank * 128);
                for (int i = 0; i < nch; ++i, ++g) {
                    const int s = (int)(g % NSTAGE);
                    if (g >= NSTAGE)
                        MBARRIER_WAIT_PARITY(sb + MB_MMA(s), (int)((g / NSTAGE - 1) & 1));
                    const uint32_t stage = sb + SMEM_STAGE0 + (uint32_t)s * STAGE_BYTES;
                    if (rank == 0)
                        MBARRIER_EXPECT_TX(sb + MB_LD(s), CHUNK_TX_BYTES);
                    tma_cg2(stage + OFF_A, &tma_a, i * KC, arow, sb + MB_LD(s));
                    tma_cg2(stage + OFF_B, &tma_b, i * KC, brow, sb + MB_LD(s));
                }
            }
        }
    } else if (wid == 0 && rank == 0) {
        // ================= MMA issue warp (leader only) =================
        long g = 0;
        for (int j = 0; j < ntiles; ++j) {
            const int b = j & 1;
            if (j >= 2)
                MBARRIER_WAIT_PARITY(sb + MB_EPI(b), ((j - 2) >> 1) & 1);
            tc_fence_after();                     // order vs epilogue TMEM reads
            const uint32_t dbuf = tmem + (uint32_t)b * 256;
            for (int i = 0; i < nch; ++i, ++g) {
                const int s = (int)(g % NSTAGE);
                MBARRIER_WAIT_PARITY(sb + MB_LD(s), (int)((g / NSTAGE) & 1));
                if (elect_one()) {
                    const uint32_t stage = sb + SMEM_STAGE0 + (uint32_t)s * STAGE_BYTES;
                    const uint64_t ad = make_desc(stage + OFF_A);
                    const uint64_t bd = make_desc(stage + OFF_B);
                    uint32_t en = (i != 0) ? 1u : 0u;
#pragma unroll
                    for (int kk = 0; kk < 4; ++kk) {
                        mma_ss_cg2(dbuf, ad + kk*2, bd + kk*2, MMA_IDESC, en);
                        en = 1;
                    }
                    tc_commit_mc_cg2(sb + MB_MMA(s), 0x3);
                    if (i == nch - 1) tc_commit_mc_cg2(sb + MB_TILE(b), 0x3);
                }
            }
        }
    } else if (wid == 2 || wid == 3) {
        // ================= spare warps: wd fp32->fp16 convert (MODE 1 only) ======
        // Consumed only by GEMM2, which is stream-ordered after this kernel.
        if (MODE == 1) {
            const long stride = (long)(2 * NCLUSTERS) * 64;
            for (long i = (long)blockIdx.x * 64 + (tid - 64); i < wd_n4; i += stride) {
                float4 v = wd_src[i];
                wd_dst[2*i]   = __floats2half2_rn(v.x, v.y);
                wd_dst[2*i+1] = __floats2half2_rn(v.z, v.w);
            }
        }
    } else if (wid >= 4) {
        // ================= epilogue warpgroup (warps 4-7, 128 threads) ===========
        const int et = tid - 128;                 // 0..127 -> D row within CTA
        for (int j = 0; j < ntiles; ++j) {
            const int b = j & 1;
            MBARRIER_WAIT_PARITY(sb + MB_TILE(b), (j >> 1) & 1);
            tc_fence_after();
            const int q = cid + NCLUSTERS * j;
            const int pmx = q & 15, nb = q >> 4;
            const uint32_t tb = tmem + (uint32_t)b * 256;
            const int m = (pmx * 2 + (int)rank) * BM + et;
            if (MODE == 1) {
                fp16* hh = H + (size_t)m * ldout + (size_t)nb * 128;
#pragma unroll
                for (int c0 = 0; c0 < 128; c0 += 32) {
                    uint32_t gr[32], ur[32];
                    tc_ld32(gr, tb + c0);
                    tc_ld32(ur, tb + 128 + c0);
                    tc_wait_ld();
                    uint32_t hp[16];
#pragma unroll
                    for (int jj = 0; jj < 16; ++jj) {
                        float g0 = __uint_as_float(gr[2*jj]);
                        float g1 = __uint_as_float(gr[2*jj+1]);
                        float u0 = __uint_as_float(ur[2*jj]);
                        float u1 = __uint_as_float(ur[2*jj+1]);
                        float h0 = g0 * u0 / (1.0f + __expf(-g0));
                        float h1 = g1 * u1 / (1.0f + __expf(-g1));
                        __half2 hv = __floats2half2_rn(h0, h1);
                        hp[jj] = *reinterpret_cast<uint32_t*>(&hv);
                    }
#pragma unroll
                    for (int v = 0; v < 4; ++v) {
                        uint4 vh = make_uint4(hp[4*v], hp[4*v+1], hp[4*v+2], hp[4*v+3]);
                        *reinterpret_cast<uint4*>(hh + c0 + v * 8) = vh;
                    }
                }
            } else {
                float* co = Cout + (size_t)m * ldout + (size_t)nb * 256;
#pragma unroll
                for (int c0 = 0; c0 < 256; c0 += 32) {
                    uint32_t dr[32];
                    tc_ld32(dr, tb + c0);
                    tc_wait_ld();
#pragma unroll
                    for (int v = 0; v < 8; ++v) {
                        float4 f = make_float4(__uint_as_float(dr[4*v]),
                                               __uint_as_float(dr[4*v+1]),
                                               __uint_as_float(dr[4*v+2]),
                                               __uint_as_float(dr[4*v+3]));
                        *reinterpret_cast<float4*>(co + c0 + v * 4) = f;
                    }
                }
            }
            tc_fence_before();
            if (rank == 0) { MBARRIER_ARRIVE_LOCAL(sb + MB_EPI(b)); }
            else           { MBARRIER_ARRIVE_CLUSTER(sb + MB_EPI(b), 0); }
        }
    }
    __syncthreads();
    CLUSTER_SYNC();
    if (wid == 0) {
        tc_relinquish_cg2();
        tc_dealloc_cg2(tmem, 512);
    }
    CLUSTER_SYNC();

#else
    // ---------------- SIMT fallback (plain sm_103 target; never the picked cubin) ----
    // wd convert first (MODE 1) so GEMM2 fallback sees converted weights.
    if (MODE == 1) {
        const long stride = (long)(2 * NCLUSTERS) * NTHREADS;
        for (long i = (long)blockIdx.x * NTHREADS + tid; i < wd_n4; i += stride) {
            float4 v = wd_src[i];
            wd_dst[2*i]   = __floats2half2_rn(v.x, v.y);
            wd_dst[2*i+1] = __floats2half2_rn(v.z, v.w);
        }
        __syncthreads();
    }

    float* fA  = reinterpret_cast<float*>(smem);          // [8][128]
    float* fB0 = fA  + 8 * 128;
    float* fB1 = fB0 + 8 * 128;
    const int tx = tid & 15;
    const int ty = (tid >> 4) & 15;
    const int lr = (tid & 255) >> 1;
    const int lc = (tid & 1) << 2;

    for (int j = 0; j < ntiles; ++j) {
        const int q = cid + NCLUSTERS * j;
        const int pmx = q & 15, nb = q >> 4;
        const int mbx = pmx * 2 + (int)rank;
        const fp16* a = A + (size_t)mbx * BM * K;
        const fp16* b0 = (MODE == 1)
            ? ((rank ? B1 : B) + (size_t)nb * 128 * K)
            : (B + (size_t)nb * 256 * K);
        const fp16* b1 = (MODE == 1) ? b0 : (B + ((size_t)nb * 256 + 128) * K);

        float acc0[8][8], acc1[8][8];
#pragma unroll
        for (int i = 0; i < 8; i++)
#pragma unroll
            for (int jj = 0; jj < 8; jj++) { acc0[i][jj] = 0.0f; acc1[i][jj] = 0.0f; }

        for (int k0 = 0; k0 < K; k0 += 8) {
            __syncthreads();
            if (tid < 256) {
#pragma unroll
                for (int c = 0; c < 4; ++c) {
                    int k = k0 + lc + c;
                    size_t off = (size_t)lr * K + k;
                    fA [(lc + c) * 128 + lr] = __half2float(a[off]);
                    fB0[(lc + c) * 128 + lr] = __half2float(b0[off]);
                    fB1[(lc + c) * 128 + lr] = __half2float(b1[off]);
                }
            }
            __syncthreads();
            if (tid < 256) {
#pragma unroll
                for (int k = 0; k < 8; k++) {
                    float ra[8], rb0[8], rb1[8];
#pragma unroll
                    for (int i = 0; i < 8; i++) ra[i]  = fA [k * 128 + ty * 8 + i];
#pragma unroll
                    for (int jj = 0; jj < 8; jj++) { rb0[jj] = fB0[k * 128 + tx * 8 + jj]; rb1[jj] = fB1[k * 128 + tx * 8 + jj]; }
#pragma unroll
                    for (int i = 0; i < 8; i++)
#pragma unroll
                        for (int jj = 0; jj < 8; jj++) {
                            acc0[i][jj] = fmaf(ra[i], rb0[jj], acc0[i][jj]);
                            acc1[i][jj] = fmaf(ra[i], rb1[jj], acc1[i][jj]);
                        }
                }
            }
        }
        if (tid < 256) {
            if (MODE == 1) {
#pragma unroll
                for (int i = 0; i < 8; i++) {
                    int m = mbx * BM + ty * 8 + i;
                    fp16* hh = H + (size_t)m * ldout + (size_t)nb * 128 + tx * 8;
#pragma unroll
                    for (int jj = 0; jj < 8; jj++) {
                        float g = acc0[i][jj], u = acc1[i][jj];
                        float h = g * u / (1.0f + __expf(-g));
                        hh[jj] = __float2half(h);
                    }
                }
            } else {
#pragma unroll
                for (int i = 0; i < 8; i++) {
                    int m = mbx * BM + ty * 8 + i;
                    float* co = Cout + (size_t)m * ldout + (size_t)nb * 256 + tx * 8;
#pragma unroll
                    for (int jj = 0; jj < 8; jj++) { co[jj] = acc0[i][jj]; co[128 + jj] = acc1[i][jj]; }
                }
            }
        }
        __syncthreads();
    }
#endif
}

// ======================= fp32 -> fp16 convert =======================
__global__ void convert_kernel(const float4* __restrict__ src,
                               __half2* __restrict__ dst, long n4)
{
    long i = (long)blockIdx.x * blockDim.x + threadIdx.x;
    if (i >= n4) return;
    float4 v = src[i];
    dst[2*i]   = __floats2half2_rn(v.x, v.y);
    dst[2*i+1] = __floats2half2_rn(v.z, v.w);
}

// ======================= host: tensormap building =======================

typedef CUresult (*EncodeTiledFn)(
    CUtensorMap*, CUtensorMapDataType, cuuint32_t, void*,
    const cuuint64_t*, const cuuint64_t*, const cuuint32_t*, const cuuint32_t*,
    CUtensorMapInterleave, CUtensorMapSwizzle, CUtensorMapL2promotion,
    CUtensorMapFloatOOBfill);

static void build_map(EncodeTiledFn enc, CUtensorMap* m, void* base,
                      unsigned long long dim0, unsigned long long dim1)
{
    cuuint64_t dims[3]    = {dim0, dim1, 1};
    cuuint64_t strides[2] = {dim0 * 2ull, dim0 * dim1 * 2ull};
    cuuint32_t box[3]     = {KC, BM, 1};          // 64 fp16 = 128B (SW128 atom), 128 rows
    cuuint32_t es[3]      = {1, 1, 1};
    enc(m, CU_TENSOR_MAP_DATA_TYPE_FLOAT16, 3, base, dims, strides, box, es,
        CU_TENSOR_MAP_INTERLEAVE_NONE, CU_TENSOR_MAP_SWIZZLE_128B,
        CU_TENSOR_MAP_L2_PROMOTION_L2_128B, CU_TENSOR_MAP_FLOAT_OOB_FILL_NONE);
}

// ======================= launch =======================
extern "C" void kernel_launch(void* const* d_in, const int* in_sizes, int n_in,
                              void* d_out, int out_size)
{
    const float* x   = (const float*)d_in[0];
    const float* wgu = (const float*)d_in[1];
    const float* wd  = (const float*)d_in[2];
    float* out       = (float*)d_out;

    fp16 *xc, *wguc, *wdc, *hc;
    cudaGetSymbolAddress((void**)&xc,  g_x);
    cudaGetSymbolAddress((void**)&wguc, g_wgu);
    cudaGetSymbolAddress((void**)&wdc, g_wd);
    cudaGetSymbolAddress((void**)&hc,  g_h);

    // driver entry point for tensormap encoding (avoids -lcuda link dependency)
    void* fn = nullptr;
    cudaDriverEntryPointQueryResult qr;
    cudaGetDriverEntryPoint("cuTensorMapEncodeTiled", &fn, cudaEnableDefault, &qr);
    EncodeTiledFn enc = (EncodeTiledFn)fn;

    CUtensorMap map_x, map_wgu, map_h, map_wd;
    build_map(enc, &map_x,   xc,   H_DIM, M_DIM);          // [4096, 4096]
    build_map(enc, &map_wgu, wguc, H_DIM, 2ull * I_DIM);   // [4096, 22016]
    build_map(enc, &map_h,   hc,   I_DIM, M_DIM);          // [11008, 4096]
    build_map(enc, &map_wd,  wdc,  I_DIM, H_DIM);          // [11008, 4096]

    cudaFuncSetAttribute(mlp_gemm<0>, cudaFuncAttributeMaxDynamicSharedMemorySize, SMEM_TOTAL);
    cudaFuncSetAttribute(mlp_gemm<1>, cudaFuncAttributeMaxDynamicSharedMemorySize, SMEM_TOTAL);

    // convert x + wgu to fp16 up-front (needed by GEMM1). wd is converted
    // INSIDE GEMM1 by its spare warps (overlapped with the mainloop).
    {
        long n4 = (long)M_DIM * H_DIM / 4;
        convert_kernel<<<(unsigned)((n4 + 255) / 256), 256>>>(
            (const float4*)x, (__half2*)xc, n4);
    }
    {
        long n4 = (long)2 * I_DIM * H_DIM / 4;
        convert_kernel<<<(unsigned)((n4 + 255) / 256), 256>>>(
            (const float4*)wgu, (__half2*)wguc, n4);
    }

    const long wd_n4 = (long)H_DIM * I_DIM / 4;

    // GEMM1 (fused SwiGLU -> h fp16, + wd convert on spare warps)
    mlp_gemm<1><<<dim3(2 * NCLUSTERS, 1, 1), NTHREADS, SMEM_TOTAL>>>(
        map_x, map_wgu,
        xc, wguc, wguc + (size_t)I_DIM * H_DIM,
        H_DIM, I_DIM,
        nullptr, hc,
        (const float4*)wd, (__half2*)wdc, wd_n4);

    // GEMM2: out = h @ Wd^T
    mlp_gemm<0><<<dim3(2 * NCLUSTERS, 1, 1), NTHREADS, SMEM_TOTAL>>>(
        map_h, map_wd,
        hc, wdc, nullptr,
        I_DIM, H_DIM,
        out, nullptr,
        nullptr, nullptr, 0);
}